// round 5
// baseline (speedup 1.0000x reference)
#include <cuda_runtime.h>
#include <math.h>
#include <float.h>

// ---------------- problem constants ----------------
#define CH   512
#define HW   4096
constexpr long long CHW = (long long)CH * HW;
constexpr long long CC  = (long long)CH * CH;
constexpr long long PQ  = (long long)HW * HW;

// ---------------- device scratch ----------------
__device__ float g_Fcent[4 * 2097152];
__device__ float g_means[4 * 512];
__device__ float g_Cov[4 * 262144];
__device__ float g_sigma[4];
__device__ float g_Ybuf[2 * 1048576];
__device__ float g_Zbuf[2 * 1048576];
__device__ float g_Tm[1048576];
__device__ float g_W[1048576];
__device__ float g_Cm[2 * 262144];
__device__ float g_NC[4 * 2097152];
__device__ float g_NSt[2 * 2097152];
__device__ float g_snorm[2 * 4096];
__device__ float g_rk[2 * 4096];
__device__ float g_M0[33554432];
__device__ float g_Tb[33554432];
__device__ int   g_idx[2 * 4096];
__device__ float g_pbs[2 * 16 * 4096];
__device__ int   g_pbi[2 * 16 * 4096];
__device__ float g_reasT[2 * 2097152];

// ---------------- packed f32x2 helpers ----------------
typedef unsigned long long u64;
__device__ __forceinline__ void ffma2(u64 &d, u64 a, u64 b) {
    asm("fma.rn.f32x2 %0, %1, %2, %0;" : "+l"(d) : "l"(a), "l"(b));
}
__device__ __forceinline__ float2 unpack2(u64 v) {
    float2 f; asm("mov.b64 {%0, %1}, %2;" : "=f"(f.x), "=f"(f.y) : "l"(v)); return f;
}

// ---------------- double-buffered SGEMM, A pre-duplicated in smem ----------------
// C = alpha * op(A) @ op(B) (+ diagAdd on diagonal) (+ bias[row])
// !TA: A is [M,K] row-major ; TA: A is [K,M] row-major.
// !TB: B is [K,N] row-major ; TB: B is [N,K] row-major.
// As smem stores each A value duplicated: As[kk][2m]=As[kk][2m+1]=A[m][kk],
// so the inner loop reads packed f32x2 A operands with a single LDS.64 (no MOVs).
template<int BM, int BN, int BK, int TM, int TN, bool TA, bool TB>
__device__ __forceinline__ void sgemm_tile(
    const float* __restrict__ Ab, const float* __restrict__ Bb, float* __restrict__ Cb,
    int M, int N, int K, float alpha, float diagAdd, const float* __restrict__ bias)
{
    constexpr int THREADS = (BM / TM) * (BN / TN);
    constexpr int LA4 = BM * BK / (4 * THREADS);
    constexpr int LB4 = BN * BK / (4 * THREADS);
    __shared__ float As[2][BK][2 * BM + 4];   // duplicated pairs
    __shared__ float Bs[2][BK][BN + 4];
    const int tid  = threadIdx.x;
    const int tcol = tid % (BN / TN);
    const int trow = tid / (BN / TN);
    const int m0 = blockIdx.y * BM;
    const int n0 = blockIdx.x * BN;

    float4 stA[LA4], stB[LB4];

    auto loadA = [&](int k0) {
#pragma unroll
        for (int l = 0; l < LA4; l++) {
            int i = tid + l * THREADS;
            if (TA) { int kk = i / (BM / 4); int m = (i % (BM / 4)) * 4;
                      stA[l] = *(const float4*)&Ab[(long long)(k0 + kk) * M + m0 + m]; }
            else    { int m = i / (BK / 4); int kk = (i % (BK / 4)) * 4;
                      stA[l] = *(const float4*)&Ab[(long long)(m0 + m) * K + k0 + kk]; }
        }
    };
    auto loadB = [&](int k0) {
#pragma unroll
        for (int l = 0; l < LB4; l++) {
            int i = tid + l * THREADS;
            if (TB) { int n = i / (BK / 4); int kk = (i % (BK / 4)) * 4;
                      stB[l] = *(const float4*)&Bb[(long long)(n0 + n) * K + k0 + kk]; }
            else    { int kk = i / (BN / 4); int n = (i % (BN / 4)) * 4;
                      stB[l] = *(const float4*)&Bb[(long long)(k0 + kk) * N + n0 + n]; }
        }
    };
    auto storeA = [&](int buf) {
#pragma unroll
        for (int l = 0; l < LA4; l++) {
            int i = tid + l * THREADS;
            if (TA) {
                int kk = i / (BM / 4); int m = (i % (BM / 4)) * 4;
                float4 d0; d0.x = stA[l].x; d0.y = stA[l].x; d0.z = stA[l].y; d0.w = stA[l].y;
                float4 d1; d1.x = stA[l].z; d1.y = stA[l].z; d1.z = stA[l].w; d1.w = stA[l].w;
                *(float4*)&As[buf][kk][2 * m]     = d0;
                *(float4*)&As[buf][kk][2 * m + 4] = d1;
            } else {
                int m = i / (BK / 4); int kk = (i % (BK / 4)) * 4;
                float2 v;
                v.x = stA[l].x; v.y = stA[l].x; *(float2*)&As[buf][kk + 0][2 * m] = v;
                v.x = stA[l].y; v.y = stA[l].y; *(float2*)&As[buf][kk + 1][2 * m] = v;
                v.x = stA[l].z; v.y = stA[l].z; *(float2*)&As[buf][kk + 2][2 * m] = v;
                v.x = stA[l].w; v.y = stA[l].w; *(float2*)&As[buf][kk + 3][2 * m] = v;
            }
        }
    };
    auto storeB = [&](int buf) {
#pragma unroll
        for (int l = 0; l < LB4; l++) {
            int i = tid + l * THREADS;
            if (TB) { int n = i / (BK / 4); int kk = (i % (BK / 4)) * 4;
                      Bs[buf][kk + 0][n] = stB[l].x; Bs[buf][kk + 1][n] = stB[l].y;
                      Bs[buf][kk + 2][n] = stB[l].z; Bs[buf][kk + 3][n] = stB[l].w; }
            else    { int kk = i / (BN / 4); int n = (i % (BN / 4)) * 4;
                      *(float4*)&Bs[buf][kk][n] = stB[l]; }
        }
    };

    u64 acc[TM][TN / 2];
#pragma unroll
    for (int i = 0; i < TM; i++)
#pragma unroll
        for (int j = 0; j < TN / 2; j++) acc[i][j] = 0ull;

    loadA(0); loadB(0);
    storeA(0); storeB(0);
    __syncthreads();

    int buf = 0;
    for (int k0 = 0; k0 < K; k0 += BK) {
        const bool has_next = (k0 + BK < K);
        if (has_next) { loadA(k0 + BK); loadB(k0 + BK); }
#pragma unroll
        for (int kk = 0; kk < BK; kk++) {
            u64 ra2[TM];
#pragma unroll
            for (int i = 0; i < TM; i++)
                ra2[i] = *(const u64*)&As[buf][kk][2 * (trow * TM + i)];
            u64 rb2[TN / 2];
#pragma unroll
            for (int j4 = 0; j4 < TN / 4; j4++) {
                ulonglong2 b2 = *(const ulonglong2*)&Bs[buf][kk][tcol * TN + j4 * 4];
                rb2[j4 * 2 + 0] = b2.x; rb2[j4 * 2 + 1] = b2.y;
            }
#pragma unroll
            for (int i = 0; i < TM; i++)
#pragma unroll
                for (int j = 0; j < TN / 2; j++) ffma2(acc[i][j], ra2[i], rb2[j]);
        }
        if (has_next) { storeA(buf ^ 1); storeB(buf ^ 1); }
        __syncthreads();
        buf ^= 1;
    }

#pragma unroll
    for (int i = 0; i < TM; i++) {
        int gm = m0 + trow * TM + i;
        float bv = bias ? bias[gm] : 0.f;
#pragma unroll
        for (int j = 0; j < TN / 2; j++) {
            float2 v = unpack2(acc[i][j]);
            int gn = n0 + tcol * TN + 2 * j;
            float x = alpha * v.x + bv; if (gm == gn)     x += diagAdd;
            float y = alpha * v.y + bv; if (gm == gn + 1) y += diagAdd;
            float2 o; o.x = x; o.y = y;
            *(float2*)&Cb[(long long)gm * N + gn] = o;
        }
    }
}

template<int BM, int BN, int BK, int TM, int TN, bool TA, bool TB>
__global__ void sgemm_kernel(const float* __restrict__ A, const float* __restrict__ B,
                             float* __restrict__ C,
                             int M, int N, int K,
                             long long sA, long long sB, long long sC,
                             float alpha, float diagAdd,
                             const float* __restrict__ bias, int biasStride)
{
    const float* Ab = A + (long long)blockIdx.z * sA;
    const float* Bb = B + (long long)blockIdx.z * sB;
    float* Cb = C + (long long)blockIdx.z * sC;
    const float* bb = bias ? bias + (long long)blockIdx.z * biasStride : nullptr;
    sgemm_tile<BM, BN, BK, TM, TN, TA, TB>(Ab, Bb, Cb, M, N, K, alpha, diagAdd, bb);
}

// Merged NS update: z<4 -> Yn[z] = Y[z]@T[z] ; z>=4 -> Zn[z-4] = T[z-4]@Z[z-4]
__global__ void ns_yz_kernel(const float* __restrict__ Y, const float* __restrict__ T,
                             const float* __restrict__ Z,
                             float* __restrict__ Yn, float* __restrict__ Zn)
{
    int z = blockIdx.z;
    const float *Ab, *Bb; float* Cb;
    if (z < 4) { Ab = Y + (long long)z * CC;       Bb = T + (long long)z * CC;       Cb = Yn + (long long)z * CC; }
    else       { Ab = T + (long long)(z - 4) * CC; Bb = Z + (long long)(z - 4) * CC; Cb = Zn + (long long)(z - 4) * CC; }
    sgemm_tile<64, 64, 8, 8, 8, false, false>(Ab, Bb, Cb, 512, 512, 512, 1.f, 0.f, nullptr);
}

// ---------------- per-channel mean + center ----------------
__global__ void center_kernel(const float* __restrict__ content, const float* __restrict__ style,
                              float* __restrict__ Fcent, float* __restrict__ means)
{
    int c = blockIdx.x, g = blockIdx.y;
    const float* src = (g < 2 ? content + (long long)g * CHW : style + (long long)(g - 2) * CHW)
                       + (long long)c * HW;
    __shared__ float red[256];
    float s = 0.f;
    for (int i = threadIdx.x; i < HW; i += 256) s += src[i];
    red[threadIdx.x] = s; __syncthreads();
    for (int st = 128; st > 0; st >>= 1) {
        if (threadIdx.x < st) red[threadIdx.x] += red[threadIdx.x + st];
        __syncthreads();
    }
    float mean = red[0] * (1.f / HW);
    if (threadIdx.x == 0) means[g * CH + c] = mean;
    float* dst = Fcent + (long long)g * CHW + (long long)c * HW;
    for (int i = threadIdx.x; i < HW; i += 256) dst[i] = src[i] - mean;
}

// ---------------- power iteration for lambda_max ----------------
__global__ void power_kernel(const float* __restrict__ Cov, float* __restrict__ sigma)
{
    int g = blockIdx.x;
    const float* A = Cov + (long long)g * CC;
    __shared__ float v[CH];
    __shared__ float red[CH];
    int t = threadIdx.x;
    v[t] = 1.f + 1e-4f * t;
    __syncthreads();
    float lam = 0.f;
    for (int it = 0; it < 40; it++) {
        float acc = 0.f;
        for (int k = 0; k < CH; k++) acc = fmaf(A[(long long)k * CH + t], v[k], acc);
        __syncthreads();
        red[t] = acc * acc; __syncthreads();
        for (int st = 256; st > 0; st >>= 1) {
            if (t < st) red[t] += red[t + st];
            __syncthreads();
        }
        float n2 = red[0];
        lam = sqrtf(n2);
        float inv = (n2 > 0.f) ? rsqrtf(n2) : 0.f;
        __syncthreads();
        v[t] = acc * inv;
        __syncthreads();
    }
    if (t == 0) sigma[g] = lam * 1.02f + 1e-20f;
}

// ---------------- Newton-Schulz init / rescale ----------------
__global__ void ns_init_kernel(const float* __restrict__ Cov, const float* __restrict__ sigma,
                               float* __restrict__ Y, float* __restrict__ Z)
{
    long long i = (long long)blockIdx.x * blockDim.x + threadIdx.x;
    if (i >= 4 * CC) return;
    int g = (int)(i / CC);
    long long r = i % CC;
    int row = (int)(r / CH), col = (int)(r % CH);
    Y[i] = Cov[i] / sigma[g];
    Z[i] = (row == col) ? 1.f : 0.f;
}

__global__ void scale_kernel(const float* __restrict__ Y, const float* __restrict__ Z,
                             const float* __restrict__ sigma,
                             float* __restrict__ W, float* __restrict__ Cm)
{
    long long i = (long long)blockIdx.x * blockDim.x + threadIdx.x;
    if (i >= 4 * CC) return;
    int g = (int)(i / CC);
    float sq = sqrtf(sigma[g]);
    W[i] = Z[i] / sq;
    if (g >= 2) Cm[i - 2 * CC] = Y[i] * sq;
}

// ---------------- transpose whitened style to [pix][c] ----------------
__global__ void transpose_kernel(const float* __restrict__ NC, float* __restrict__ NSt)
{
    __shared__ float tile[32][33];
    int b = blockIdx.z;
    int p0 = blockIdx.x * 32, c0 = blockIdx.y * 32;
    const float* src = NC + (long long)(2 + b) * CHW;
    tile[threadIdx.y][threadIdx.x] = src[(long long)(c0 + threadIdx.y) * HW + p0 + threadIdx.x];
    __syncthreads();
    NSt[(long long)b * CHW + (long long)(p0 + threadIdx.y) * CH + c0 + threadIdx.x] =
        tile[threadIdx.x][threadIdx.y];
}

// ---------------- per-pixel squared norms ----------------
__global__ void snorm_kernel(const float* __restrict__ NSt, float* __restrict__ snorm)
{
    int gw = (blockIdx.x * blockDim.x + threadIdx.x) >> 5;
    int lane = threadIdx.x & 31;
    if (gw >= 2 * HW) return;
    int b = gw / HW, p = gw % HW;
    const float* row = NSt + (long long)b * CHW + (long long)p * CH;
    float s = 0.f;
    for (int c = lane; c < CH; c += 32) { float v = row[c]; s = fmaf(v, v, s); }
    for (int o = 16; o > 0; o >>= 1) s += __shfl_down_sync(0xffffffff, s, o);
    if (lane == 0) snorm[b * HW + p] = s;
}

__global__ void rknorm_kernel(const float* __restrict__ snorm, float* __restrict__ rk)
{
    int i = blockIdx.x * blockDim.x + threadIdx.x;
    if (i >= 2 * HW) return;
    int b = i / HW, p = i % HW;
    int py = p >> 6, px = p & 63;
    float sum = 0.f;
    for (int u = -1; u <= 1; u++)
        for (int v = -1; v <= 1; v++) {
            int yy = py + u, xx = px + v;
            if ((unsigned)yy < 64u && (unsigned)xx < 64u) sum += snorm[b * HW + yy * 64 + xx];
        }
    rk[i] = 1.f / (sqrtf(sum) + 1e-5f);
}

// ---------------- horizontal diagonal 3-box ----------------
__global__ void boxh_kernel(const float* __restrict__ M0, float* __restrict__ Tb)
{
    long long i = (long long)blockIdx.x * 256 + threadIdx.x;
    int b = blockIdx.y;
    const float* M = M0 + (long long)b * PQ;
    int p = (int)(i >> 12);
    int q = (int)(i & 4095);
    int px = p & 63, qx = q & 63;
    float s = 0.f;
#pragma unroll
    for (int v = -1; v <= 1; v++) {
        if ((unsigned)(px + v) < 64u && (unsigned)(qx + v) < 64u) s += M[i + (long long)v * 4097];
    }
    Tb[(long long)b * PQ + i] = s;
}

// ---------------- vertical diagonal 3-box + partial argmax ----------------
__global__ void argmax_part_kernel(const float* __restrict__ Tb, const float* __restrict__ rk,
                                   float* __restrict__ pbs, int* __restrict__ pbi)
{
    int b = blockIdx.z;
    int q = blockIdx.x * 256 + threadIdx.x;
    int pc = blockIdx.y;
    __shared__ float srk[256];
    srk[threadIdx.x] = rk[b * HW + pc * 256 + threadIdx.x];
    __syncthreads();
    const float* T = Tb + (long long)b * PQ;
    float best = -FLT_MAX; int bi = 0;
    for (int pp = 0; pp < 256; pp++) {
        int p = pc * 256 + pp;
        float s = 0.f;
#pragma unroll
        for (int u = -1; u <= 1; u++) {
            int row = p + 64 * u, col = q + 64 * u;
            if ((unsigned)row < (unsigned)HW && (unsigned)col < (unsigned)HW)
                s += T[(long long)row * HW + col];
        }
        float sc = s * srk[pp];
        if (sc > best) { best = sc; bi = p; }
    }
    pbs[(b * 16 + pc) * HW + q] = best;
    pbi[(b * 16 + pc) * HW + q] = bi;
}

__global__ void argmax_comb_kernel(const float* __restrict__ pbs, const int* __restrict__ pbi,
                                   int* __restrict__ idx)
{
    int i = blockIdx.x * 256 + threadIdx.x;
    if (i >= 2 * HW) return;
    int b = i / HW, q = i % HW;
    float best = -FLT_MAX; int bi = 0;
    for (int k = 0; k < 16; k++) {
        float s = pbs[(b * 16 + k) * HW + q];
        int p = pbi[(b * 16 + k) * HW + q];
        if (s > best || (s == best && p < bi)) { best = s; bi = p; }
    }
    idx[b * HW + q] = bi;
}

// ---------------- gather best patches + overlap-add ----------------
__global__ void gather_kernel(const float* __restrict__ NSt, const int* __restrict__ idx,
                              float* __restrict__ reasT)
{
    int b = blockIdx.y, pix = blockIdx.x;
    int Y = pix >> 6, X = pix & 63;
    __shared__ int sp[9];
    if (threadIdx.x < 9) {
        int dx = threadIdx.x / 3, dy = threadIdx.x % 3;
        int y = Y + 1 - dx, x = X + 1 - dy;
        int pos = -1;
        if ((unsigned)y < 64u && (unsigned)x < 64u) {
            int p = idx[b * HW + y * 64 + x];
            int sy = (p >> 6) + dx - 1, sx = (p & 63) + dy - 1;
            if ((unsigned)sy < 64u && (unsigned)sx < 64u) pos = sy * 64 + sx;
        }
        sp[threadIdx.x] = pos;
    }
    __syncthreads();
    int cy = (Y == 0 || Y == 63) ? 2 : 3;
    int cx = (X == 0 || X == 63) ? 2 : 3;
    float inv = 1.f / (float)(cy * cx);
    const float* base = NSt + (long long)b * CHW;
    float* out = reasT + (long long)b * CHW + (long long)pix * CH;
    for (int c = threadIdx.x; c < CH; c += 128) {
        float a = 0.f;
#pragma unroll
        for (int k = 0; k < 9; k++) {
            int pos = sp[k];
            if (pos >= 0) a += base[(long long)pos * CH + c];
        }
        out[c] = a * inv;
    }
}

// ---------------- host orchestration ----------------
extern "C" void kernel_launch(void* const* d_in, const int* in_sizes, int n_in,
                              void* d_out, int out_size)
{
    (void)in_sizes; (void)n_in; (void)out_size;
    const float* content = (const float*)d_in[0];
    const float* style   = (const float*)d_in[1];
    float* out = (float*)d_out;

    float *Fcent, *means, *Cov, *sigma, *Yb, *Zb, *Tm, *W, *Cm, *NC, *NSt, *snorm, *rk, *M0, *Tb, *pbs, *reasT;
    int *idx, *pbi;
    cudaGetSymbolAddress((void**)&Fcent, g_Fcent);
    cudaGetSymbolAddress((void**)&means, g_means);
    cudaGetSymbolAddress((void**)&Cov,   g_Cov);
    cudaGetSymbolAddress((void**)&sigma, g_sigma);
    cudaGetSymbolAddress((void**)&Yb,    g_Ybuf);
    cudaGetSymbolAddress((void**)&Zb,    g_Zbuf);
    cudaGetSymbolAddress((void**)&Tm,    g_Tm);
    cudaGetSymbolAddress((void**)&W,     g_W);
    cudaGetSymbolAddress((void**)&Cm,    g_Cm);
    cudaGetSymbolAddress((void**)&NC,    g_NC);
    cudaGetSymbolAddress((void**)&NSt,   g_NSt);
    cudaGetSymbolAddress((void**)&snorm, g_snorm);
    cudaGetSymbolAddress((void**)&rk,    g_rk);
    cudaGetSymbolAddress((void**)&M0,    g_M0);
    cudaGetSymbolAddress((void**)&Tb,    g_Tb);
    cudaGetSymbolAddress((void**)&idx,   g_idx);
    cudaGetSymbolAddress((void**)&pbs,   g_pbs);
    cudaGetSymbolAddress((void**)&pbi,   g_pbi);
    cudaGetSymbolAddress((void**)&reasT, g_reasT);

    // 1) center
    center_kernel<<<dim3(CH, 4), 256>>>(content, style, Fcent, means);

    // 2) covariances
    sgemm_kernel<64, 64, 8, 8, 8, false, true><<<dim3(8, 8, 4), 64>>>(
        Fcent, Fcent, Cov, 512, 512, 4096, CHW, CHW, CC, 1.f / 4095.f, 0.f, nullptr, 0);

    // 3) lambda_max
    power_kernel<<<4, 512>>>(Cov, sigma);

    // 4) Newton-Schulz (6 iterations)
    ns_init_kernel<<<4096, 256>>>(Cov, sigma, Yb, Zb);
    float* Yc = Yb;            float* Yn = Yb + 4 * CC;
    float* Zc = Zb;            float* Zn = Zb + 4 * CC;
    for (int it = 0; it < 6; it++) {
        sgemm_kernel<64, 64, 8, 8, 8, false, false><<<dim3(8, 8, 4), 64>>>(
            Zc, Yc, Tm, 512, 512, 512, CC, CC, CC, -0.5f, 1.5f, nullptr, 0);
        ns_yz_kernel<<<dim3(8, 8, 8), 64>>>(Yc, Tm, Zc, Yn, Zn);
        float* t;
        t = Yc; Yc = Yn; Yn = t;
        t = Zc; Zc = Zn; Zn = t;
    }
    // 5) rescale
    scale_kernel<<<4096, 256>>>(Yc, Zc, sigma, W, Cm);

    // 6) whitening: NC[g] = W[g] @ Fcent[g]
    sgemm_kernel<128, 128, 8, 8, 8, false, false><<<dim3(32, 4, 4), 256>>>(
        W, Fcent, NC, 512, 4096, 512, CC, CHW, CHW, 1.f, 0.f, nullptr, 0);

    // 7) transpose + patch norms
    transpose_kernel<<<dim3(128, 16, 2), dim3(32, 32)>>>(NC, NSt);
    snorm_kernel<<<1024, 256>>>(NSt, snorm);
    rknorm_kernel<<<32, 256>>>(snorm, rk);

    // 8) M0[b] = ns[b]^T @ nc[b]
    sgemm_kernel<128, 128, 8, 8, 8, true, false><<<dim3(32, 32, 2), 256>>>(
        NC + 2 * CHW, NC, M0, 4096, 4096, 512, CHW, CHW, PQ, 1.f, 0.f, nullptr, 0);

    // 9) box filter + argmax
    boxh_kernel<<<dim3(65536, 2), 256>>>(M0, Tb);
    argmax_part_kernel<<<dim3(16, 16, 2), 256>>>(Tb, rk, pbs, pbi);
    argmax_comb_kernel<<<32, 256>>>(pbs, pbi, idx);

    // 10) gather + overlap-add
    gather_kernel<<<dim3(4096, 2), 128>>>(NSt, idx, reasT);

    // 11) color
    sgemm_kernel<128, 128, 8, 8, 8, false, true><<<dim3(32, 4, 2), 256>>>(
        Cm, reasT, out, 512, 4096, 512, CC, CHW, CHW, 1.f, 0.f, means + 2 * CH, CH);
}

// round 6
// speedup vs baseline: 1.2206x; 1.2206x over previous
#include <cuda_runtime.h>
#include <math.h>
#include <float.h>

// ---------------- problem constants ----------------
#define CH   512
#define HW   4096
constexpr long long CHW = (long long)CH * HW;
constexpr long long CC  = (long long)CH * CH;
constexpr long long PQ  = (long long)HW * HW;

// ---------------- device scratch ----------------
__device__ float g_Fcent[4 * 2097152];
__device__ float g_means[4 * 512];
__device__ float g_Cov[4 * 262144];
__device__ float g_sigma[4];
__device__ float g_Ybuf[2 * 1048576];
__device__ float g_Zbuf[2 * 1048576];
__device__ float g_Tm[1048576];
__device__ float g_W[1048576];
__device__ float g_Cm[2 * 262144];
__device__ float g_NC[4 * 2097152];
__device__ float g_NSt[2 * 2097152];
__device__ float g_snorm[2 * 4096];
__device__ float g_rk[2 * 4096];
__device__ float g_M0[33554432];
__device__ float g_Tb[33554432];
__device__ int   g_idx[2 * 4096];
__device__ float g_pbs[2 * 16 * 4096];
__device__ int   g_pbi[2 * 16 * 4096];
__device__ float g_reasT[2 * 2097152];

// ---------------- packed f32x2 helpers ----------------
typedef unsigned long long u64;
__device__ __forceinline__ u64 pack2(float x) {
    u64 r; asm("mov.b64 %0, {%1, %1};" : "=l"(r) : "f"(x)); return r;
}
__device__ __forceinline__ void ffma2(u64 &d, u64 a, u64 b) {
    asm("fma.rn.f32x2 %0, %1, %2, %3;" : "=l"(d) : "l"(a), "l"(b), "l"(d));
}
__device__ __forceinline__ float2 unpack2(u64 v) {
    float2 f; asm("mov.b64 {%0, %1}, %2;" : "=f"(f.x), "=f"(f.y) : "l"(v)); return f;
}

// ---------------- double-buffered pipelined SGEMM (f32x2 inner loop) ----------------
// C = alpha * op(A) @ op(B) (+ diagAdd on diagonal) (+ bias[row])
// !TA: A is [M,K] row-major ; TA: A is [K,M] row-major.
// !TB: B is [K,N] row-major ; TB: B is [N,K] row-major.
template<int BM, int BN, int BK, int TM, int TN, bool TA, bool TB>
__device__ __forceinline__ void sgemm_tile(
    const float* __restrict__ Ab, const float* __restrict__ Bb, float* __restrict__ Cb,
    int M, int N, int K, float alpha, float diagAdd, const float* __restrict__ bias)
{
    constexpr int THREADS = (BM / TM) * (BN / TN);
    constexpr int LA4 = BM * BK / (4 * THREADS);
    constexpr int LB4 = BN * BK / (4 * THREADS);
    __shared__ float As[2][BK][BM + 4];
    __shared__ float Bs[2][BK][BN + 4];
    const int tid  = threadIdx.x;
    const int tcol = tid % (BN / TN);
    const int trow = tid / (BN / TN);
    const int m0 = blockIdx.y * BM;
    const int n0 = blockIdx.x * BN;

    float4 stA[LA4], stB[LB4];

    auto loadA = [&](int k0) {
#pragma unroll
        for (int l = 0; l < LA4; l++) {
            int i = tid + l * THREADS;
            if (TA) { int kk = i / (BM / 4); int m = (i % (BM / 4)) * 4;
                      stA[l] = *(const float4*)&Ab[(long long)(k0 + kk) * M + m0 + m]; }
            else    { int m = i / (BK / 4); int kk = (i % (BK / 4)) * 4;
                      stA[l] = *(const float4*)&Ab[(long long)(m0 + m) * K + k0 + kk]; }
        }
    };
    auto loadB = [&](int k0) {
#pragma unroll
        for (int l = 0; l < LB4; l++) {
            int i = tid + l * THREADS;
            if (TB) { int n = i / (BK / 4); int kk = (i % (BK / 4)) * 4;
                      stB[l] = *(const float4*)&Bb[(long long)(n0 + n) * K + k0 + kk]; }
            else    { int kk = i / (BN / 4); int n = (i % (BN / 4)) * 4;
                      stB[l] = *(const float4*)&Bb[(long long)(k0 + kk) * N + n0 + n]; }
        }
    };
    auto storeA = [&](int buf) {
#pragma unroll
        for (int l = 0; l < LA4; l++) {
            int i = tid + l * THREADS;
            if (TA) { int kk = i / (BM / 4); int m = (i % (BM / 4)) * 4;
                      *(float4*)&As[buf][kk][m] = stA[l]; }
            else    { int m = i / (BK / 4); int kk = (i % (BK / 4)) * 4;
                      As[buf][kk + 0][m] = stA[l].x; As[buf][kk + 1][m] = stA[l].y;
                      As[buf][kk + 2][m] = stA[l].z; As[buf][kk + 3][m] = stA[l].w; }
        }
    };
    auto storeB = [&](int buf) {
#pragma unroll
        for (int l = 0; l < LB4; l++) {
            int i = tid + l * THREADS;
            if (TB) { int n = i / (BK / 4); int kk = (i % (BK / 4)) * 4;
                      Bs[buf][kk + 0][n] = stB[l].x; Bs[buf][kk + 1][n] = stB[l].y;
                      Bs[buf][kk + 2][n] = stB[l].z; Bs[buf][kk + 3][n] = stB[l].w; }
            else    { int kk = i / (BN / 4); int n = (i % (BN / 4)) * 4;
                      *(float4*)&Bs[buf][kk][n] = stB[l]; }
        }
    };

    u64 acc[TM][TN / 2];
#pragma unroll
    for (int i = 0; i < TM; i++)
#pragma unroll
        for (int j = 0; j < TN / 2; j++) acc[i][j] = 0ull;

    loadA(0); loadB(0);
    storeA(0); storeB(0);
    __syncthreads();

    int buf = 0;
    for (int k0 = 0; k0 < K; k0 += BK) {
        const bool has_next = (k0 + BK < K);
        if (has_next) { loadA(k0 + BK); loadB(k0 + BK); }
#pragma unroll
        for (int kk = 0; kk < BK; kk++) {
            float ra[TM];
#pragma unroll
            for (int i4 = 0; i4 < TM / 4; i4++) {
                float4 a4 = *(const float4*)&As[buf][kk][trow * TM + i4 * 4];
                ra[i4 * 4 + 0] = a4.x; ra[i4 * 4 + 1] = a4.y;
                ra[i4 * 4 + 2] = a4.z; ra[i4 * 4 + 3] = a4.w;
            }
            u64 rb2[TN / 2];
#pragma unroll
            for (int j4 = 0; j4 < TN / 4; j4++) {
                ulonglong2 b2 = *(const ulonglong2*)&Bs[buf][kk][tcol * TN + j4 * 4];
                rb2[j4 * 2 + 0] = b2.x; rb2[j4 * 2 + 1] = b2.y;
            }
#pragma unroll
            for (int i = 0; i < TM; i++) {
                u64 a2 = pack2(ra[i]);
#pragma unroll
                for (int j = 0; j < TN / 2; j++) ffma2(acc[i][j], a2, rb2[j]);
            }
        }
        if (has_next) { storeA(buf ^ 1); storeB(buf ^ 1); }
        __syncthreads();
        buf ^= 1;
    }

#pragma unroll
    for (int i = 0; i < TM; i++) {
        int gm = m0 + trow * TM + i;
        float bv = bias ? bias[gm] : 0.f;
#pragma unroll
        for (int j = 0; j < TN / 2; j++) {
            float2 v = unpack2(acc[i][j]);
            int gn = n0 + tcol * TN + 2 * j;
            float x = alpha * v.x + bv; if (gm == gn)     x += diagAdd;
            float y = alpha * v.y + bv; if (gm == gn + 1) y += diagAdd;
            float2 o; o.x = x; o.y = y;
            *(float2*)&Cb[(long long)gm * N + gn] = o;
        }
    }
}

template<int BM, int BN, int BK, int TM, int TN, bool TA, bool TB>
__global__ void sgemm_kernel(const float* __restrict__ A, const float* __restrict__ B,
                             float* __restrict__ C,
                             int M, int N, int K,
                             long long sA, long long sB, long long sC,
                             float alpha, float diagAdd,
                             const float* __restrict__ bias, int biasStride)
{
    const float* Ab = A + (long long)blockIdx.z * sA;
    const float* Bb = B + (long long)blockIdx.z * sB;
    float* Cb = C + (long long)blockIdx.z * sC;
    const float* bb = bias ? bias + (long long)blockIdx.z * biasStride : nullptr;
    sgemm_tile<BM, BN, BK, TM, TN, TA, TB>(Ab, Bb, Cb, M, N, K, alpha, diagAdd, bb);
}

// Merged NS update: z<4 -> Yn[z] = Y[z]@T[z] ; z>=4 -> Zn[z-4] = T[z-4]@Z[z-4]
__global__ void ns_yz_kernel(const float* __restrict__ Y, const float* __restrict__ T,
                             const float* __restrict__ Z,
                             float* __restrict__ Yn, float* __restrict__ Zn)
{
    int z = blockIdx.z;
    const float *Ab, *Bb; float* Cb;
    if (z < 4) { Ab = Y + (long long)z * CC;       Bb = T + (long long)z * CC;       Cb = Yn + (long long)z * CC; }
    else       { Ab = T + (long long)(z - 4) * CC; Bb = Z + (long long)(z - 4) * CC; Cb = Zn + (long long)(z - 4) * CC; }
    sgemm_tile<64, 64, 16, 4, 4, false, false>(Ab, Bb, Cb, 512, 512, 512, 1.f, 0.f, nullptr);
}

// ---------------- per-channel mean + center ----------------
__global__ void center_kernel(const float* __restrict__ content, const float* __restrict__ style,
                              float* __restrict__ Fcent, float* __restrict__ means)
{
    int c = blockIdx.x, g = blockIdx.y;
    const float* src = (g < 2 ? content + (long long)g * CHW : style + (long long)(g - 2) * CHW)
                       + (long long)c * HW;
    __shared__ float red[256];
    float s = 0.f;
    for (int i = threadIdx.x; i < HW; i += 256) s += src[i];
    red[threadIdx.x] = s; __syncthreads();
    for (int st = 128; st > 0; st >>= 1) {
        if (threadIdx.x < st) red[threadIdx.x] += red[threadIdx.x + st];
        __syncthreads();
    }
    float mean = red[0] * (1.f / HW);
    if (threadIdx.x == 0) means[g * CH + c] = mean;
    float* dst = Fcent + (long long)g * CHW + (long long)c * HW;
    for (int i = threadIdx.x; i < HW; i += 256) dst[i] = src[i] - mean;
}

// ---------------- power iteration for lambda_max ----------------
__global__ void power_kernel(const float* __restrict__ Cov, float* __restrict__ sigma)
{
    int g = blockIdx.x;
    const float* A = Cov + (long long)g * CC;
    __shared__ float v[CH];
    __shared__ float red[CH];
    int t = threadIdx.x;
    v[t] = 1.f + 1e-4f * t;
    __syncthreads();
    float lam = 0.f;
    for (int it = 0; it < 40; it++) {
        float acc = 0.f;
        for (int k = 0; k < CH; k++) acc = fmaf(A[(long long)k * CH + t], v[k], acc);
        __syncthreads();
        red[t] = acc * acc; __syncthreads();
        for (int st = 256; st > 0; st >>= 1) {
            if (t < st) red[t] += red[t + st];
            __syncthreads();
        }
        float n2 = red[0];
        lam = sqrtf(n2);
        float inv = (n2 > 0.f) ? rsqrtf(n2) : 0.f;
        __syncthreads();
        v[t] = acc * inv;
        __syncthreads();
    }
    if (t == 0) sigma[g] = lam * 1.02f + 1e-20f;
}

// ---------------- Newton-Schulz init / rescale ----------------
__global__ void ns_init_kernel(const float* __restrict__ Cov, const float* __restrict__ sigma,
                               float* __restrict__ Y, float* __restrict__ Z)
{
    long long i = (long long)blockIdx.x * blockDim.x + threadIdx.x;
    if (i >= 4 * CC) return;
    int g = (int)(i / CC);
    long long r = i % CC;
    int row = (int)(r / CH), col = (int)(r % CH);
    Y[i] = Cov[i] / sigma[g];
    Z[i] = (row == col) ? 1.f : 0.f;
}

__global__ void scale_kernel(const float* __restrict__ Y, const float* __restrict__ Z,
                             const float* __restrict__ sigma,
                             float* __restrict__ W, float* __restrict__ Cm)
{
    long long i = (long long)blockIdx.x * blockDim.x + threadIdx.x;
    if (i >= 4 * CC) return;
    int g = (int)(i / CC);
    float sq = sqrtf(sigma[g]);
    W[i] = Z[i] / sq;
    if (g >= 2) Cm[i - 2 * CC] = Y[i] * sq;
}

// ---------------- transpose whitened style to [pix][c] ----------------
__global__ void transpose_kernel(const float* __restrict__ NC, float* __restrict__ NSt)
{
    __shared__ float tile[32][33];
    int b = blockIdx.z;
    int p0 = blockIdx.x * 32, c0 = blockIdx.y * 32;
    const float* src = NC + (long long)(2 + b) * CHW;
    tile[threadIdx.y][threadIdx.x] = src[(long long)(c0 + threadIdx.y) * HW + p0 + threadIdx.x];
    __syncthreads();
    NSt[(long long)b * CHW + (long long)(p0 + threadIdx.y) * CH + c0 + threadIdx.x] =
        tile[threadIdx.x][threadIdx.y];
}

// ---------------- per-pixel squared norms ----------------
__global__ void snorm_kernel(const float* __restrict__ NSt, float* __restrict__ snorm)
{
    int gw = (blockIdx.x * blockDim.x + threadIdx.x) >> 5;
    int lane = threadIdx.x & 31;
    if (gw >= 2 * HW) return;
    int b = gw / HW, p = gw % HW;
    const float* row = NSt + (long long)b * CHW + (long long)p * CH;
    float s = 0.f;
    for (int c = lane; c < CH; c += 32) { float v = row[c]; s = fmaf(v, v, s); }
    for (int o = 16; o > 0; o >>= 1) s += __shfl_down_sync(0xffffffff, s, o);
    if (lane == 0) snorm[b * HW + p] = s;
}

__global__ void rknorm_kernel(const float* __restrict__ snorm, float* __restrict__ rk)
{
    int i = blockIdx.x * blockDim.x + threadIdx.x;
    if (i >= 2 * HW) return;
    int b = i / HW, p = i % HW;
    int py = p >> 6, px = p & 63;
    float sum = 0.f;
    for (int u = -1; u <= 1; u++)
        for (int v = -1; v <= 1; v++) {
            int yy = py + u, xx = px + v;
            if ((unsigned)yy < 64u && (unsigned)xx < 64u) sum += snorm[b * HW + yy * 64 + xx];
        }
    rk[i] = 1.f / (sqrtf(sum) + 1e-5f);
}

// ---------------- horizontal diagonal 3-box ----------------
__global__ void boxh_kernel(const float* __restrict__ M0, float* __restrict__ Tb)
{
    long long i = (long long)blockIdx.x * 256 + threadIdx.x;
    int b = blockIdx.y;
    const float* M = M0 + (long long)b * PQ;
    int p = (int)(i >> 12);
    int q = (int)(i & 4095);
    int px = p & 63, qx = q & 63;
    float s = 0.f;
#pragma unroll
    for (int v = -1; v <= 1; v++) {
        if ((unsigned)(px + v) < 64u && (unsigned)(qx + v) < 64u) s += M[i + (long long)v * 4097];
    }
    Tb[(long long)b * PQ + i] = s;
}

// ---------------- vertical diagonal 3-box + partial argmax ----------------
__global__ void argmax_part_kernel(const float* __restrict__ Tb, const float* __restrict__ rk,
                                   float* __restrict__ pbs, int* __restrict__ pbi)
{
    int b = blockIdx.z;
    int q = blockIdx.x * 256 + threadIdx.x;
    int pc = blockIdx.y;
    __shared__ float srk[256];
    srk[threadIdx.x] = rk[b * HW + pc * 256 + threadIdx.x];
    __syncthreads();
    const float* T = Tb + (long long)b * PQ;
    float best = -FLT_MAX; int bi = 0;
    for (int pp = 0; pp < 256; pp++) {
        int p = pc * 256 + pp;
        float s = 0.f;
#pragma unroll
        for (int u = -1; u <= 1; u++) {
            int row = p + 64 * u, col = q + 64 * u;
            if ((unsigned)row < (unsigned)HW && (unsigned)col < (unsigned)HW)
                s += T[(long long)row * HW + col];
        }
        float sc = s * srk[pp];
        if (sc > best) { best = sc; bi = p; }
    }
    pbs[(b * 16 + pc) * HW + q] = best;
    pbi[(b * 16 + pc) * HW + q] = bi;
}

__global__ void argmax_comb_kernel(const float* __restrict__ pbs, const int* __restrict__ pbi,
                                   int* __restrict__ idx)
{
    int i = blockIdx.x * 256 + threadIdx.x;
    if (i >= 2 * HW) return;
    int b = i / HW, q = i % HW;
    float best = -FLT_MAX; int bi = 0;
    for (int k = 0; k < 16; k++) {
        float s = pbs[(b * 16 + k) * HW + q];
        int p = pbi[(b * 16 + k) * HW + q];
        if (s > best || (s == best && p < bi)) { best = s; bi = p; }
    }
    idx[b * HW + q] = bi;
}

// ---------------- gather best patches + overlap-add ----------------
__global__ void gather_kernel(const float* __restrict__ NSt, const int* __restrict__ idx,
                              float* __restrict__ reasT)
{
    int b = blockIdx.y, pix = blockIdx.x;
    int Y = pix >> 6, X = pix & 63;
    __shared__ int sp[9];
    if (threadIdx.x < 9) {
        int dx = threadIdx.x / 3, dy = threadIdx.x % 3;
        int y = Y + 1 - dx, x = X + 1 - dy;
        int pos = -1;
        if ((unsigned)y < 64u && (unsigned)x < 64u) {
            int p = idx[b * HW + y * 64 + x];
            int sy = (p >> 6) + dx - 1, sx = (p & 63) + dy - 1;
            if ((unsigned)sy < 64u && (unsigned)sx < 64u) pos = sy * 64 + sx;
        }
        sp[threadIdx.x] = pos;
    }
    __syncthreads();
    int cy = (Y == 0 || Y == 63) ? 2 : 3;
    int cx = (X == 0 || X == 63) ? 2 : 3;
    float inv = 1.f / (float)(cy * cx);
    const float* base = NSt + (long long)b * CHW;
    float* out = reasT + (long long)b * CHW + (long long)pix * CH;
    for (int c = threadIdx.x; c < CH; c += 128) {
        float a = 0.f;
#pragma unroll
        for (int k = 0; k < 9; k++) {
            int pos = sp[k];
            if (pos >= 0) a += base[(long long)pos * CH + c];
        }
        out[c] = a * inv;
    }
}

// ---------------- host orchestration ----------------
extern "C" void kernel_launch(void* const* d_in, const int* in_sizes, int n_in,
                              void* d_out, int out_size)
{
    (void)in_sizes; (void)n_in; (void)out_size;
    const float* content = (const float*)d_in[0];
    const float* style   = (const float*)d_in[1];
    float* out = (float*)d_out;

    float *Fcent, *means, *Cov, *sigma, *Yb, *Zb, *Tm, *W, *Cm, *NC, *NSt, *snorm, *rk, *M0, *Tb, *pbs, *reasT;
    int *idx, *pbi;
    cudaGetSymbolAddress((void**)&Fcent, g_Fcent);
    cudaGetSymbolAddress((void**)&means, g_means);
    cudaGetSymbolAddress((void**)&Cov,   g_Cov);
    cudaGetSymbolAddress((void**)&sigma, g_sigma);
    cudaGetSymbolAddress((void**)&Yb,    g_Ybuf);
    cudaGetSymbolAddress((void**)&Zb,    g_Zbuf);
    cudaGetSymbolAddress((void**)&Tm,    g_Tm);
    cudaGetSymbolAddress((void**)&W,     g_W);
    cudaGetSymbolAddress((void**)&Cm,    g_Cm);
    cudaGetSymbolAddress((void**)&NC,    g_NC);
    cudaGetSymbolAddress((void**)&NSt,   g_NSt);
    cudaGetSymbolAddress((void**)&snorm, g_snorm);
    cudaGetSymbolAddress((void**)&rk,    g_rk);
    cudaGetSymbolAddress((void**)&M0,    g_M0);
    cudaGetSymbolAddress((void**)&Tb,    g_Tb);
    cudaGetSymbolAddress((void**)&idx,   g_idx);
    cudaGetSymbolAddress((void**)&pbs,   g_pbs);
    cudaGetSymbolAddress((void**)&pbi,   g_pbi);
    cudaGetSymbolAddress((void**)&reasT, g_reasT);

    // 1) center
    center_kernel<<<dim3(CH, 4), 256>>>(content, style, Fcent, means);

    // 2) covariances — R1-proven shape: 64x64 tile, TM=TN=4, 256 threads
    sgemm_kernel<64, 64, 16, 4, 4, false, true><<<dim3(8, 8, 4), 256>>>(
        Fcent, Fcent, Cov, 512, 512, 4096, CHW, CHW, CC, 1.f / 4095.f, 0.f, nullptr, 0);

    // 3) lambda_max
    power_kernel<<<4, 512>>>(Cov, sigma);

    // 4) Newton-Schulz (6 iterations)
    ns_init_kernel<<<4096, 256>>>(Cov, sigma, Yb, Zb);
    float* Yc = Yb;            float* Yn = Yb + 4 * CC;
    float* Zc = Zb;            float* Zn = Zb + 4 * CC;
    for (int it = 0; it < 6; it++) {
        sgemm_kernel<64, 64, 16, 4, 4, false, false><<<dim3(8, 8, 4), 256>>>(
            Zc, Yc, Tm, 512, 512, 512, CC, CC, CC, -0.5f, 1.5f, nullptr, 0);
        ns_yz_kernel<<<dim3(8, 8, 8), 256>>>(Yc, Tm, Zc, Yn, Zn);
        float* t;
        t = Yc; Yc = Yn; Yn = t;
        t = Zc; Zc = Zn; Zn = t;
    }
    // 5) rescale
    scale_kernel<<<4096, 256>>>(Yc, Zc, sigma, W, Cm);

    // 6) whitening: NC[g] = W[g] @ Fcent[g]
    sgemm_kernel<128, 128, 16, 8, 8, false, false><<<dim3(32, 4, 4), 256>>>(
        W, Fcent, NC, 512, 4096, 512, CC, CHW, CHW, 1.f, 0.f, nullptr, 0);

    // 7) transpose + patch norms
    transpose_kernel<<<dim3(128, 16, 2), dim3(32, 32)>>>(NC, NSt);
    snorm_kernel<<<1024, 256>>>(NSt, snorm);
    rknorm_kernel<<<32, 256>>>(snorm, rk);

    // 8) M0[b] = ns[b]^T @ nc[b]
    sgemm_kernel<128, 128, 16, 8, 8, true, false><<<dim3(32, 32, 2), 256>>>(
        NC + 2 * CHW, NC, M0, 4096, 4096, 512, CHW, CHW, PQ, 1.f, 0.f, nullptr, 0);

    // 9) box filter + argmax
    boxh_kernel<<<dim3(65536, 2), 256>>>(M0, Tb);
    argmax_part_kernel<<<dim3(16, 16, 2), 256>>>(Tb, rk, pbs, pbi);
    argmax_comb_kernel<<<32, 256>>>(pbs, pbi, idx);

    // 10) gather + overlap-add
    gather_kernel<<<dim3(4096, 2), 128>>>(NSt, idx, reasT);

    // 11) color
    sgemm_kernel<128, 128, 16, 8, 8, false, true><<<dim3(32, 4, 2), 256>>>(
        Cm, reasT, out, 512, 4096, 512, CC, CHW, CHW, 1.f, 0.f, means + 2 * CH, CH);
}

// round 8
// speedup vs baseline: 1.2382x; 1.0144x over previous
#include <cuda_runtime.h>
#include <math.h>
#include <float.h>
#include <stdint.h>

// ---------------- problem constants ----------------
#define CH   512
#define HW   4096
constexpr long long CHW = (long long)CH * HW;
constexpr long long CC  = (long long)CH * CH;
constexpr long long PQ  = (long long)HW * HW;

// ---------------- device scratch ----------------
__device__ float g_Fcent[4 * 2097152];
__device__ float g_means[4 * 512];
__device__ float g_Cov[4 * 262144];
__device__ float g_sigma[4];
__device__ float g_Ybuf[2 * 1048576];
__device__ float g_Zbuf[2 * 1048576];
__device__ float g_Tm[1048576];
__device__ float g_W[1048576];
__device__ float g_Cm[2 * 262144];
__device__ float g_NC[4 * 2097152];
__device__ float g_NSt[2 * 2097152];
__device__ float g_NCth[2 * 2097152];   // content^T hi (tf32)
__device__ float g_NCtl[2 * 2097152];   // content^T lo
__device__ float g_NSth[2 * 2097152];   // style^T hi
__device__ float g_NStl[2 * 2097152];   // style^T lo
__device__ float g_snorm[2 * 4096];
__device__ float g_rk[2 * 4096];
__device__ float g_M0[33554432];
__device__ float g_Tb[33554432];
__device__ int   g_idx[2 * 4096];
__device__ float g_pbs[2 * 16 * 4096];
__device__ int   g_pbi[2 * 16 * 4096];
__device__ float g_reasT[2 * 2097152];

// ---------------- packed f32x2 helpers (SIMT GEMM stages) ----------------
typedef unsigned long long u64;
__device__ __forceinline__ u64 pack2(float x) {
    u64 r; asm("mov.b64 %0, {%1, %1};" : "=l"(r) : "f"(x)); return r;
}
__device__ __forceinline__ void ffma2(u64 &d, u64 a, u64 b) {
    asm("fma.rn.f32x2 %0, %1, %2, %3;" : "=l"(d) : "l"(a), "l"(b), "l"(d));
}
__device__ __forceinline__ float2 unpack2(u64 v) {
    float2 f; asm("mov.b64 {%0, %1}, %2;" : "=f"(f.x), "=f"(f.y) : "l"(v)); return f;
}

__device__ __forceinline__ float tf32_rna(float x) {
    uint32_t u; asm("cvt.rna.tf32.f32 %0, %1;" : "=r"(u) : "f"(x));
    return __uint_as_float(u);
}

// ---------------- warp-level tf32 MMA (legacy HMMA path, works on sm_103) ----------------
__device__ __forceinline__ void mma_tf32(float* c, const uint32_t* a, const uint32_t* b) {
    asm volatile(
        "mma.sync.aligned.m16n8k8.row.col.f32.tf32.tf32.f32 "
        "{%0,%1,%2,%3}, {%4,%5,%6,%7}, {%8,%9}, {%0,%1,%2,%3};"
        : "+f"(c[0]), "+f"(c[1]), "+f"(c[2]), "+f"(c[3])
        : "r"(a[0]), "r"(a[1]), "r"(a[2]), "r"(a[3]), "r"(b[0]), "r"(b[1]));
}

// ---------------- M0 tensor-core kernel (3xTF32) ----------------
// D[128 x 128] per block = A[128 x 512] * B[128 x 512]^T
// A rows = style pixels (m), B rows = content pixels (n), both [row][K] row-major.
#define SKP 20   // smem row stride in floats (16 data + 4 pad) — conflict-free frag loads
__global__ void __launch_bounds__(256, 2) m0_mma_kernel(
    const float* __restrict__ Ah, const float* __restrict__ Al,
    const float* __restrict__ Bh, const float* __restrict__ Bl,
    float* __restrict__ M0out)
{
    __shared__ float sAh[128 * SKP], sAl[128 * SKP];
    __shared__ float sBh[128 * SKP], sBl[128 * SKP];
    const int tid  = threadIdx.x;
    const int wid  = tid >> 5, lane = tid & 31;
    const int g    = lane >> 2, t = lane & 3;     // groupID / tid-in-group
    const int wm   = wid & 3, wn = wid >> 2;      // warp tile: rows wm*32, cols wn*64
    const int m0   = blockIdx.y * 128, n0 = blockIdx.x * 128;
    const int b    = blockIdx.z;
    const float* Ahb = Ah + (long long)b * CHW;
    const float* Alb = Al + (long long)b * CHW;
    const float* Bhb = Bh + (long long)b * CHW;
    const float* Blb = Bl + (long long)b * CHW;

    float acc[2][8][4];
#pragma unroll
    for (int i = 0; i < 2; i++)
#pragma unroll
        for (int j = 0; j < 8; j++)
#pragma unroll
            for (int k = 0; k < 4; k++) acc[i][j][k] = 0.f;

    for (int kt = 0; kt < 32; kt++) {            // K = 512 in chunks of 16
        __syncthreads();
#pragma unroll
        for (int tt = 0; tt < 2; tt++) {
            int idx = tid + tt * 256;
            int row = idx >> 2, c4 = (idx & 3) * 4;
            long long gA = (long long)(m0 + row) * CH + kt * 16 + c4;
            long long gB = (long long)(n0 + row) * CH + kt * 16 + c4;
            *(float4*)&sAh[row * SKP + c4] = *(const float4*)&Ahb[gA];
            *(float4*)&sAl[row * SKP + c4] = *(const float4*)&Alb[gA];
            *(float4*)&sBh[row * SKP + c4] = *(const float4*)&Bhb[gB];
            *(float4*)&sBl[row * SKP + c4] = *(const float4*)&Blb[gB];
        }
        __syncthreads();
#pragma unroll
        for (int ks = 0; ks < 16; ks += 8) {
            uint32_t afh[2][4], afl[2][4];
#pragma unroll
            for (int mt = 0; mt < 2; mt++) {
                int r  = wm * 32 + mt * 16;
                int i0 = (r + g) * SKP + ks + t;
                int i8 = (r + g + 8) * SKP + ks + t;
                afh[mt][0] = __float_as_uint(sAh[i0]);
                afh[mt][1] = __float_as_uint(sAh[i8]);
                afh[mt][2] = __float_as_uint(sAh[i0 + 4]);
                afh[mt][3] = __float_as_uint(sAh[i8 + 4]);
                afl[mt][0] = __float_as_uint(sAl[i0]);
                afl[mt][1] = __float_as_uint(sAl[i8]);
                afl[mt][2] = __float_as_uint(sAl[i0 + 4]);
                afl[mt][3] = __float_as_uint(sAl[i8 + 4]);
            }
#pragma unroll
            for (int nt = 0; nt < 8; nt++) {
                int bb = (wn * 64 + nt * 8 + g) * SKP + ks + t;
                uint32_t bfh[2] = { __float_as_uint(sBh[bb]), __float_as_uint(sBh[bb + 4]) };
                uint32_t bfl[2] = { __float_as_uint(sBl[bb]), __float_as_uint(sBl[bb + 4]) };
#pragma unroll
                for (int mt = 0; mt < 2; mt++) {
                    mma_tf32(acc[mt][nt], afh[mt], bfh);
                    mma_tf32(acc[mt][nt], afh[mt], bfl);
                    mma_tf32(acc[mt][nt], afl[mt], bfh);
                }
            }
        }
    }

#pragma unroll
    for (int mt = 0; mt < 2; mt++) {
        int row = m0 + wm * 32 + mt * 16 + g;
        float* r0 = M0out + (long long)b * PQ + (long long)row * HW;
        float* r1 = r0 + 8ll * HW;
#pragma unroll
        for (int nt = 0; nt < 8; nt++) {
            int col = n0 + wn * 64 + nt * 8 + 2 * t;
            float2 v0; v0.x = acc[mt][nt][0]; v0.y = acc[mt][nt][1];
            float2 v1; v1.x = acc[mt][nt][2]; v1.y = acc[mt][nt][3];
            *(float2*)&r0[col] = v0;
            *(float2*)&r1[col] = v1;
        }
    }
}

// ---------------- double-buffered pipelined SGEMM (f32x2 inner loop) ----------------
template<int BM, int BN, int BK, int TM, int TN, bool TA, bool TB>
__device__ __forceinline__ void sgemm_tile(
    const float* __restrict__ Ab, const float* __restrict__ Bb, float* __restrict__ Cb,
    int M, int N, int K, float alpha, float diagAdd, const float* __restrict__ bias)
{
    constexpr int THREADS = (BM / TM) * (BN / TN);
    constexpr int LA4 = BM * BK / (4 * THREADS);
    constexpr int LB4 = BN * BK / (4 * THREADS);
    __shared__ float As[2][BK][BM + 4];
    __shared__ float Bs[2][BK][BN + 4];
    const int tid  = threadIdx.x;
    const int tcol = tid % (BN / TN);
    const int trow = tid / (BN / TN);
    const int m0 = blockIdx.y * BM;
    const int n0 = blockIdx.x * BN;

    float4 stA[LA4], stB[LB4];

    auto loadA = [&](int k0) {
#pragma unroll
        for (int l = 0; l < LA4; l++) {
            int i = tid + l * THREADS;
            if (TA) { int kk = i / (BM / 4); int m = (i % (BM / 4)) * 4;
                      stA[l] = *(const float4*)&Ab[(long long)(k0 + kk) * M + m0 + m]; }
            else    { int m = i / (BK / 4); int kk = (i % (BK / 4)) * 4;
                      stA[l] = *(const float4*)&Ab[(long long)(m0 + m) * K + k0 + kk]; }
        }
    };
    auto loadB = [&](int k0) {
#pragma unroll
        for (int l = 0; l < LB4; l++) {
            int i = tid + l * THREADS;
            if (TB) { int n = i / (BK / 4); int kk = (i % (BK / 4)) * 4;
                      stB[l] = *(const float4*)&Bb[(long long)(n0 + n) * K + k0 + kk]; }
            else    { int kk = i / (BN / 4); int n = (i % (BN / 4)) * 4;
                      stB[l] = *(const float4*)&Bb[(long long)(k0 + kk) * N + n0 + n]; }
        }
    };
    auto storeA = [&](int buf) {
#pragma unroll
        for (int l = 0; l < LA4; l++) {
            int i = tid + l * THREADS;
            if (TA) { int kk = i / (BM / 4); int m = (i % (BM / 4)) * 4;
                      *(float4*)&As[buf][kk][m] = stA[l]; }
            else    { int m = i / (BK / 4); int kk = (i % (BK / 4)) * 4;
                      As[buf][kk + 0][m] = stA[l].x; As[buf][kk + 1][m] = stA[l].y;
                      As[buf][kk + 2][m] = stA[l].z; As[buf][kk + 3][m] = stA[l].w; }
        }
    };
    auto storeB = [&](int buf) {
#pragma unroll
        for (int l = 0; l < LB4; l++) {
            int i = tid + l * THREADS;
            if (TB) { int n = i / (BK / 4); int kk = (i % (BK / 4)) * 4;
                      Bs[buf][kk + 0][n] = stB[l].x; Bs[buf][kk + 1][n] = stB[l].y;
                      Bs[buf][kk + 2][n] = stB[l].z; Bs[buf][kk + 3][n] = stB[l].w; }
            else    { int kk = i / (BN / 4); int n = (i % (BN / 4)) * 4;
                      *(float4*)&Bs[buf][kk][n] = stB[l]; }
        }
    };

    u64 acc[TM][TN / 2];
#pragma unroll
    for (int i = 0; i < TM; i++)
#pragma unroll
        for (int j = 0; j < TN / 2; j++) acc[i][j] = 0ull;

    loadA(0); loadB(0);
    storeA(0); storeB(0);
    __syncthreads();

    int buf = 0;
    for (int k0 = 0; k0 < K; k0 += BK) {
        const bool has_next = (k0 + BK < K);
        if (has_next) { loadA(k0 + BK); loadB(k0 + BK); }
#pragma unroll
        for (int kk = 0; kk < BK; kk++) {
            float ra[TM];
#pragma unroll
            for (int i4 = 0; i4 < TM / 4; i4++) {
                float4 a4 = *(const float4*)&As[buf][kk][trow * TM + i4 * 4];
                ra[i4 * 4 + 0] = a4.x; ra[i4 * 4 + 1] = a4.y;
                ra[i4 * 4 + 2] = a4.z; ra[i4 * 4 + 3] = a4.w;
            }
            u64 rb2[TN / 2];
#pragma unroll
            for (int j4 = 0; j4 < TN / 4; j4++) {
                ulonglong2 b2 = *(const ulonglong2*)&Bs[buf][kk][tcol * TN + j4 * 4];
                rb2[j4 * 2 + 0] = b2.x; rb2[j4 * 2 + 1] = b2.y;
            }
#pragma unroll
            for (int i = 0; i < TM; i++) {
                u64 a2 = pack2(ra[i]);
#pragma unroll
                for (int j = 0; j < TN / 2; j++) ffma2(acc[i][j], a2, rb2[j]);
            }
        }
        if (has_next) { storeA(buf ^ 1); storeB(buf ^ 1); }
        __syncthreads();
        buf ^= 1;
    }

#pragma unroll
    for (int i = 0; i < TM; i++) {
        int gm = m0 + trow * TM + i;
        float bv = bias ? bias[gm] : 0.f;
#pragma unroll
        for (int j = 0; j < TN / 2; j++) {
            float2 v = unpack2(acc[i][j]);
            int gn = n0 + tcol * TN + 2 * j;
            float x = alpha * v.x + bv; if (gm == gn)     x += diagAdd;
            float y = alpha * v.y + bv; if (gm == gn + 1) y += diagAdd;
            float2 o; o.x = x; o.y = y;
            *(float2*)&Cb[(long long)gm * N + gn] = o;
        }
    }
}

template<int BM, int BN, int BK, int TM, int TN, bool TA, bool TB>
__global__ void sgemm_kernel(const float* __restrict__ A, const float* __restrict__ B,
                             float* __restrict__ C,
                             int M, int N, int K,
                             long long sA, long long sB, long long sC,
                             float alpha, float diagAdd,
                             const float* __restrict__ bias, int biasStride)
{
    const float* Ab = A + (long long)blockIdx.z * sA;
    const float* Bb = B + (long long)blockIdx.z * sB;
    float* Cb = C + (long long)blockIdx.z * sC;
    const float* bb = bias ? bias + (long long)blockIdx.z * biasStride : nullptr;
    sgemm_tile<BM, BN, BK, TM, TN, TA, TB>(Ab, Bb, Cb, M, N, K, alpha, diagAdd, bb);
}

__global__ void ns_yz_kernel(const float* __restrict__ Y, const float* __restrict__ T,
                             const float* __restrict__ Z,
                             float* __restrict__ Yn, float* __restrict__ Zn)
{
    int z = blockIdx.z;
    const float *Ab, *Bb; float* Cb;
    if (z < 4) { Ab = Y + (long long)z * CC;       Bb = T + (long long)z * CC;       Cb = Yn + (long long)z * CC; }
    else       { Ab = T + (long long)(z - 4) * CC; Bb = Z + (long long)(z - 4) * CC; Cb = Zn + (long long)(z - 4) * CC; }
    sgemm_tile<64, 64, 16, 4, 4, false, false>(Ab, Bb, Cb, 512, 512, 512, 1.f, 0.f, nullptr);
}

// ---------------- per-channel mean + center ----------------
__global__ void center_kernel(const float* __restrict__ content, const float* __restrict__ style,
                              float* __restrict__ Fcent, float* __restrict__ means)
{
    int c = blockIdx.x, g = blockIdx.y;
    const float* src = (g < 2 ? content + (long long)g * CHW : style + (long long)(g - 2) * CHW)
                       + (long long)c * HW;
    __shared__ float red[256];
    float s = 0.f;
    for (int i = threadIdx.x; i < HW; i += 256) s += src[i];
    red[threadIdx.x] = s; __syncthreads();
    for (int st = 128; st > 0; st >>= 1) {
        if (threadIdx.x < st) red[threadIdx.x] += red[threadIdx.x + st];
        __syncthreads();
    }
    float mean = red[0] * (1.f / HW);
    if (threadIdx.x == 0) means[g * CH + c] = mean;
    float* dst = Fcent + (long long)g * CHW + (long long)c * HW;
    for (int i = threadIdx.x; i < HW; i += 256) dst[i] = src[i] - mean;
}

// ---------------- power iteration ----------------
__global__ void power_kernel(const float* __restrict__ Cov, float* __restrict__ sigma)
{
    int g = blockIdx.x;
    const float* A = Cov + (long long)g * CC;
    __shared__ float v[CH];
    __shared__ float red[CH];
    int t = threadIdx.x;
    v[t] = 1.f + 1e-4f * t;
    __syncthreads();
    float lam = 0.f;
    for (int it = 0; it < 40; it++) {
        float acc = 0.f;
        for (int k = 0; k < CH; k++) acc = fmaf(A[(long long)k * CH + t], v[k], acc);
        __syncthreads();
        red[t] = acc * acc; __syncthreads();
        for (int st = 256; st > 0; st >>= 1) {
            if (t < st) red[t] += red[t + st];
            __syncthreads();
        }
        float n2 = red[0];
        lam = sqrtf(n2);
        float inv = (n2 > 0.f) ? rsqrtf(n2) : 0.f;
        __syncthreads();
        v[t] = acc * inv;
        __syncthreads();
    }
    if (t == 0) sigma[g] = lam * 1.02f + 1e-20f;
}

// ---------------- Newton-Schulz init / rescale ----------------
__global__ void ns_init_kernel(const float* __restrict__ Cov, const float* __restrict__ sigma,
                               float* __restrict__ Y, float* __restrict__ Z)
{
    long long i = (long long)blockIdx.x * blockDim.x + threadIdx.x;
    if (i >= 4 * CC) return;
    int g = (int)(i / CC);
    long long r = i % CC;
    int row = (int)(r / CH), col = (int)(r % CH);
    Y[i] = Cov[i] / sigma[g];
    Z[i] = (row == col) ? 1.f : 0.f;
}

__global__ void scale_kernel(const float* __restrict__ Y, const float* __restrict__ Z,
                             const float* __restrict__ sigma,
                             float* __restrict__ W, float* __restrict__ Cm)
{
    long long i = (long long)blockIdx.x * blockDim.x + threadIdx.x;
    if (i >= 4 * CC) return;
    int g = (int)(i / CC);
    float sq = sqrtf(sigma[g]);
    W[i] = Z[i] / sq;
    if (g >= 2) Cm[i - 2 * CC] = Y[i] * sq;
}

// ---------------- transpose + tf32 hi/lo split ----------------
__global__ void transpose_split_kernel(const float* __restrict__ NC,
                                       float* __restrict__ NSt,
                                       float* __restrict__ NCth, float* __restrict__ NCtl,
                                       float* __restrict__ NSth, float* __restrict__ NStl)
{
    __shared__ float tile[32][33];
    int g = blockIdx.z;
    int p0 = blockIdx.x * 32, c0 = blockIdx.y * 32;
    const float* src = NC + (long long)g * CHW;
    tile[threadIdx.y][threadIdx.x] = src[(long long)(c0 + threadIdx.y) * HW + p0 + threadIdx.x];
    __syncthreads();
    float x = tile[threadIdx.x][threadIdx.y];
    long long o = (long long)(g & 1) * CHW + (long long)(p0 + threadIdx.y) * CH + c0 + threadIdx.x;
    float hi = tf32_rna(x);
    float lo = tf32_rna(x - hi);
    if (g < 2) { NCth[o] = hi; NCtl[o] = lo; }
    else       { NSt[o] = x; NSth[o] = hi; NStl[o] = lo; }
}

// ---------------- per-pixel squared norms ----------------
__global__ void snorm_kernel(const float* __restrict__ NSt, float* __restrict__ snorm)
{
    int gw = (blockIdx.x * blockDim.x + threadIdx.x) >> 5;
    int lane = threadIdx.x & 31;
    if (gw >= 2 * HW) return;
    int b = gw / HW, p = gw % HW;
    const float* row = NSt + (long long)b * CHW + (long long)p * CH;
    float s = 0.f;
    for (int c = lane; c < CH; c += 32) { float v = row[c]; s = fmaf(v, v, s); }
    for (int o = 16; o > 0; o >>= 1) s += __shfl_down_sync(0xffffffff, s, o);
    if (lane == 0) snorm[b * HW + p] = s;
}

__global__ void rknorm_kernel(const float* __restrict__ snorm, float* __restrict__ rk)
{
    int i = blockIdx.x * blockDim.x + threadIdx.x;
    if (i >= 2 * HW) return;
    int b = i / HW, p = i % HW;
    int py = p >> 6, px = p & 63;
    float sum = 0.f;
    for (int u = -1; u <= 1; u++)
        for (int v = -1; v <= 1; v++) {
            int yy = py + u, xx = px + v;
            if ((unsigned)yy < 64u && (unsigned)xx < 64u) sum += snorm[b * HW + yy * 64 + xx];
        }
    rk[i] = 1.f / (sqrtf(sum) + 1e-5f);
}

// ---------------- horizontal diagonal 3-box ----------------
__global__ void boxh_kernel(const float* __restrict__ M0, float* __restrict__ Tb)
{
    long long i = (long long)blockIdx.x * 256 + threadIdx.x;
    int b = blockIdx.y;
    const float* M = M0 + (long long)b * PQ;
    int p = (int)(i >> 12);
    int q = (int)(i & 4095);
    int px = p & 63, qx = q & 63;
    float s = 0.f;
#pragma unroll
    for (int v = -1; v <= 1; v++) {
        if ((unsigned)(px + v) < 64u && (unsigned)(qx + v) < 64u) s += M[i + (long long)v * 4097];
    }
    Tb[(long long)b * PQ + i] = s;
}

// ---------------- vertical diagonal 3-box + partial argmax ----------------
__global__ void argmax_part_kernel(const float* __restrict__ Tb, const float* __restrict__ rk,
                                   float* __restrict__ pbs, int* __restrict__ pbi)
{
    int b = blockIdx.z;
    int q = blockIdx.x * 256 + threadIdx.x;
    int pc = blockIdx.y;
    __shared__ float srk[256];
    srk[threadIdx.x] = rk[b * HW + pc * 256 + threadIdx.x];
    __syncthreads();
    const float* T = Tb + (long long)b * PQ;
    float best = -FLT_MAX; int bi = 0;
    for (int pp = 0; pp < 256; pp++) {
        int p = pc * 256 + pp;
        float s = 0.f;
#pragma unroll
        for (int u = -1; u <= 1; u++) {
            int row = p + 64 * u, col = q + 64 * u;
            if ((unsigned)row < (unsigned)HW && (unsigned)col < (unsigned)HW)
                s += T[(long long)row * HW + col];
        }
        float sc = s * srk[pp];
        if (sc > best) { best = sc; bi = p; }
    }
    pbs[(b * 16 + pc) * HW + q] = best;
    pbi[(b * 16 + pc) * HW + q] = bi;
}

__global__ void argmax_comb_kernel(const float* __restrict__ pbs, const int* __restrict__ pbi,
                                   int* __restrict__ idx)
{
    int i = blockIdx.x * 256 + threadIdx.x;
    if (i >= 2 * HW) return;
    int b = i / HW, q = i % HW;
    float best = -FLT_MAX; int bi = 0;
    for (int k = 0; k < 16; k++) {
        float s = pbs[(b * 16 + k) * HW + q];
        int p = pbi[(b * 16 + k) * HW + q];
        if (s > best || (s == best && p < bi)) { best = s; bi = p; }
    }
    idx[b * HW + q] = bi;
}

// ---------------- gather best patches + overlap-add ----------------
__global__ void gather_kernel(const float* __restrict__ NSt, const int* __restrict__ idx,
                              float* __restrict__ reasT)
{
    int b = blockIdx.y, pix = blockIdx.x;
    int Y = pix >> 6, X = pix & 63;
    __shared__ int sp[9];
    if (threadIdx.x < 9) {
        int dx = threadIdx.x / 3, dy = threadIdx.x % 3;
        int y = Y + 1 - dx, x = X + 1 - dy;
        int pos = -1;
        if ((unsigned)y < 64u && (unsigned)x < 64u) {
            int p = idx[b * HW + y * 64 + x];
            int sy = (p >> 6) + dx - 1, sx = (p & 63) + dy - 1;
            if ((unsigned)sy < 64u && (unsigned)sx < 64u) pos = sy * 64 + sx;
        }
        sp[threadIdx.x] = pos;
    }
    __syncthreads();
    int cy = (Y == 0 || Y == 63) ? 2 : 3;
    int cx = (X == 0 || X == 63) ? 2 : 3;
    float inv = 1.f / (float)(cy * cx);
    const float* base = NSt + (long long)b * CHW;
    float* out = reasT + (long long)b * CHW + (long long)pix * CH;
    for (int c = threadIdx.x; c < CH; c += 128) {
        float a = 0.f;
#pragma unroll
        for (int k = 0; k < 9; k++) {
            int pos = sp[k];
            if (pos >= 0) a += base[(long long)pos * CH + c];
        }
        out[c] = a * inv;
    }
}

// ---------------- host orchestration ----------------
extern "C" void kernel_launch(void* const* d_in, const int* in_sizes, int n_in,
                              void* d_out, int out_size)
{
    (void)in_sizes; (void)n_in; (void)out_size;
    const float* content = (const float*)d_in[0];
    const float* style   = (const float*)d_in[1];
    float* out = (float*)d_out;

    float *Fcent, *means, *Cov, *sigma, *Yb, *Zb, *Tm, *W, *Cm, *NC, *NSt, *snorm, *rk, *M0, *Tb, *pbs, *reasT;
    float *NCth, *NCtl, *NSth, *NStl;
    int *idx, *pbi;
    cudaGetSymbolAddress((void**)&Fcent, g_Fcent);
    cudaGetSymbolAddress((void**)&means, g_means);
    cudaGetSymbolAddress((void**)&Cov,   g_Cov);
    cudaGetSymbolAddress((void**)&sigma, g_sigma);
    cudaGetSymbolAddress((void**)&Yb,    g_Ybuf);
    cudaGetSymbolAddress((void**)&Zb,    g_Zbuf);
    cudaGetSymbolAddress((void**)&Tm,    g_Tm);
    cudaGetSymbolAddress((void**)&W,     g_W);
    cudaGetSymbolAddress((void**)&Cm,    g_Cm);
    cudaGetSymbolAddress((void**)&NC,    g_NC);
    cudaGetSymbolAddress((void**)&NSt,   g_NSt);
    cudaGetSymbolAddress((void**)&NCth,  g_NCth);
    cudaGetSymbolAddress((void**)&NCtl,  g_NCtl);
    cudaGetSymbolAddress((void**)&NSth,  g_NSth);
    cudaGetSymbolAddress((void**)&NStl,  g_NStl);
    cudaGetSymbolAddress((void**)&snorm, g_snorm);
    cudaGetSymbolAddress((void**)&rk,    g_rk);
    cudaGetSymbolAddress((void**)&M0,    g_M0);
    cudaGetSymbolAddress((void**)&Tb,    g_Tb);
    cudaGetSymbolAddress((void**)&idx,   g_idx);
    cudaGetSymbolAddress((void**)&pbs,   g_pbs);
    cudaGetSymbolAddress((void**)&pbi,   g_pbi);
    cudaGetSymbolAddress((void**)&reasT, g_reasT);

    // 1) center
    center_kernel<<<dim3(CH, 4), 256>>>(content, style, Fcent, means);

    // 2) covariances
    sgemm_kernel<64, 64, 16, 4, 4, false, true><<<dim3(8, 8, 4), 256>>>(
        Fcent, Fcent, Cov, 512, 512, 4096, CHW, CHW, CC, 1.f / 4095.f, 0.f, nullptr, 0);

    // 3) lambda_max
    power_kernel<<<4, 512>>>(Cov, sigma);

    // 4) Newton-Schulz (6 iterations)
    ns_init_kernel<<<4096, 256>>>(Cov, sigma, Yb, Zb);
    float* Yc = Yb;            float* Yn = Yb + 4 * CC;
    float* Zc = Zb;            float* Zn = Zb + 4 * CC;
    for (int it = 0; it < 6; it++) {
        sgemm_kernel<64, 64, 16, 4, 4, false, false><<<dim3(8, 8, 4), 256>>>(
            Zc, Yc, Tm, 512, 512, 512, CC, CC, CC, -0.5f, 1.5f, nullptr, 0);
        ns_yz_kernel<<<dim3(8, 8, 8), 256>>>(Yc, Tm, Zc, Yn, Zn);
        float* t;
        t = Yc; Yc = Yn; Yn = t;
        t = Zc; Zc = Zn; Zn = t;
    }
    // 5) rescale
    scale_kernel<<<4096, 256>>>(Yc, Zc, sigma, W, Cm);

    // 6) whitening: NC[g] = W[g] @ Fcent[g]
    sgemm_kernel<128, 128, 16, 8, 8, false, false><<<dim3(32, 4, 4), 256>>>(
        W, Fcent, NC, 512, 4096, 512, CC, CHW, CHW, 1.f, 0.f, nullptr, 0);

    // 7) transpose + tf32 split + patch norms
    transpose_split_kernel<<<dim3(128, 16, 4), dim3(32, 32)>>>(NC, NSt, NCth, NCtl, NSth, NStl);
    snorm_kernel<<<1024, 256>>>(NSt, snorm);
    rknorm_kernel<<<32, 256>>>(snorm, rk);

    // 8) M0[b] = ns[b]^T @ nc[b] via warp-level tf32 mma (3xTF32)
    m0_mma_kernel<<<dim3(32, 32, 2), 256>>>(NSth, NStl, NCth, NCtl, M0);

    // 9) box filter + argmax
    boxh_kernel<<<dim3(65536, 2), 256>>>(M0, Tb);
    argmax_part_kernel<<<dim3(16, 16, 2), 256>>>(Tb, rk, pbs, pbi);
    argmax_comb_kernel<<<32, 256>>>(pbs, pbi, idx);

    // 10) gather + overlap-add
    gather_kernel<<<dim3(4096, 2), 128>>>(NSt, idx, reasT);

    // 11) color
    sgemm_kernel<128, 128, 16, 8, 8, false, true><<<dim3(32, 4, 2), 256>>>(
        Cm, reasT, out, 512, 4096, 512, CC, CHW, CHW, 1.f, 0.f, means + 2 * CH, CH);
}

// round 9
// speedup vs baseline: 1.3147x; 1.0618x over previous
#include <cuda_runtime.h>
#include <math.h>
#include <float.h>
#include <stdint.h>

// ---------------- problem constants ----------------
#define CH   512
#define HW   4096
constexpr long long CHW = (long long)CH * HW;
constexpr long long CC  = (long long)CH * CH;
constexpr long long PQ  = (long long)HW * HW;

// ---------------- device scratch ----------------
__device__ float g_Fcent[4 * 2097152];
__device__ float g_means[4 * 512];
__device__ float g_Cov[4 * 262144];
__device__ float g_sigma[4];
__device__ float g_Ybuf[2 * 1048576];
__device__ float g_Zbuf[2 * 1048576];
__device__ float g_Tm[1048576];
__device__ float g_W[1048576];
__device__ float g_Cm[2 * 262144];
__device__ float g_NC[4 * 2097152];
__device__ float g_NSt[2 * 2097152];
__device__ float g_NCth[2 * 2097152];
__device__ float g_NCtl[2 * 2097152];
__device__ float g_NSth[2 * 2097152];
__device__ float g_NStl[2 * 2097152];
__device__ float g_snorm[2 * 4096];
__device__ float g_rk[2 * 4096];
__device__ float g_M0[33554432];
__device__ float g_Tb[33554432];
__device__ int   g_idx[2 * 4096];
__device__ float g_pbs[2 * 16 * 4096];
__device__ int   g_pbi[2 * 16 * 4096];
__device__ float g_reasT[2 * 2097152];

// ---------------- packed f32x2 helpers (SIMT GEMM stages) ----------------
typedef unsigned long long u64;
__device__ __forceinline__ u64 pack2(float x) {
    u64 r; asm("mov.b64 %0, {%1, %1};" : "=l"(r) : "f"(x)); return r;
}
__device__ __forceinline__ void ffma2(u64 &d, u64 a, u64 b) {
    asm("fma.rn.f32x2 %0, %1, %2, %3;" : "=l"(d) : "l"(a), "l"(b), "l"(d));
}
__device__ __forceinline__ float2 unpack2(u64 v) {
    float2 f; asm("mov.b64 {%0, %1}, %2;" : "=f"(f.x), "=f"(f.y) : "l"(v)); return f;
}

__device__ __forceinline__ float tf32_rna(float x) {
    uint32_t u; asm("cvt.rna.tf32.f32 %0, %1;" : "=r"(u) : "f"(x));
    return __uint_as_float(u);
}
__device__ __forceinline__ uint32_t smem_to_u32(const void* p) {
    uint32_t a;
    asm("{ .reg .u64 t; cvta.to.shared.u64 t, %1; cvt.u32.u64 %0, t; }" : "=r"(a) : "l"(p));
    return a;
}
__device__ __forceinline__ void cp_async16(uint32_t saddr, const void* g) {
    asm volatile("cp.async.cg.shared.global [%0], [%1], 16;" :: "r"(saddr), "l"(g));
}
#define CP_COMMIT() asm volatile("cp.async.commit_group;" ::: "memory")
#define CP_WAIT1()  asm volatile("cp.async.wait_group 1;" ::: "memory")
#define CP_WAIT0()  asm volatile("cp.async.wait_group 0;" ::: "memory")

// ---------------- warp-level tf32 MMA ----------------
__device__ __forceinline__ void mma_tf32(float* c, const uint32_t* a, const uint32_t* b) {
    asm volatile(
        "mma.sync.aligned.m16n8k8.row.col.f32.tf32.tf32.f32 "
        "{%0,%1,%2,%3}, {%4,%5,%6,%7}, {%8,%9}, {%0,%1,%2,%3};"
        : "+f"(c[0]), "+f"(c[1]), "+f"(c[2]), "+f"(c[3])
        : "r"(a[0]), "r"(a[1]), "r"(a[2]), "r"(a[3]), "r"(b[0]), "r"(b[1]));
}

// ---------------- M0 tensor-core kernel (3xTF32, cp.async double-buffered) ----------------
#define SKP 20
constexpr int M0_ARR  = 128 * SKP;           // floats per operand tile
constexpr int M0_BUF  = 4 * M0_ARR;          // floats per pipeline buffer
constexpr int M0_SMEM = 2 * M0_BUF * 4;      // bytes (81920)

__global__ void __launch_bounds__(256, 2) m0_mma_kernel(
    const float* __restrict__ Ah, const float* __restrict__ Al,
    const float* __restrict__ Bh, const float* __restrict__ Bl,
    float* __restrict__ M0out)
{
    extern __shared__ float sm[];
    const uint32_t sbase = smem_to_u32(sm);
    const int tid  = threadIdx.x;
    const int wid  = tid >> 5, lane = tid & 31;
    const int g    = lane >> 2, t = lane & 3;
    const int wm   = wid & 3, wn = wid >> 2;
    const int m0   = blockIdx.y * 128, n0 = blockIdx.x * 128;
    const int b    = blockIdx.z;
    const float* arr0 = Ah + (long long)b * CHW;
    const float* arr1 = Al + (long long)b * CHW;
    const float* arr2 = Bh + (long long)b * CHW;
    const float* arr3 = Bl + (long long)b * CHW;

    // staging: 4 arrays x 128 rows x 16 floats = 2048 float4, 8 per thread
    auto stage = [&](int kt, int buf) {
#pragma unroll
        for (int tt = 0; tt < 8; tt++) {
            int idx = tid + tt * 256;
            int a   = idx >> 9;
            int r   = (idx & 511) >> 2;
            int c4  = (idx & 3) * 4;
            const float* src = (a == 0) ? arr0 : (a == 1) ? arr1 : (a == 2) ? arr2 : arr3;
            int rowbase = (a < 2) ? m0 : n0;
            const float* gp = src + (long long)(rowbase + r) * CH + kt * 16 + c4;
            uint32_t sa = sbase + (uint32_t)(buf * M0_BUF + a * M0_ARR + r * SKP + c4) * 4u;
            cp_async16(sa, gp);
        }
    };

    float acc[2][8][4];
#pragma unroll
    for (int i = 0; i < 2; i++)
#pragma unroll
        for (int j = 0; j < 8; j++)
#pragma unroll
            for (int k = 0; k < 4; k++) acc[i][j][k] = 0.f;

    stage(0, 0); CP_COMMIT();

    for (int kt = 0; kt < 32; kt++) {
        const int buf = kt & 1;
        if (kt + 1 < 32) { stage(kt + 1, buf ^ 1); CP_COMMIT(); CP_WAIT1(); }
        else             { CP_WAIT0(); }
        __syncthreads();

        const float* sAh = sm + buf * M0_BUF;
        const float* sAl = sAh + M0_ARR;
        const float* sBh = sAl + M0_ARR;
        const float* sBl = sBh + M0_ARR;
#pragma unroll
        for (int ks = 0; ks < 16; ks += 8) {
            uint32_t afh[2][4], afl[2][4];
#pragma unroll
            for (int mt = 0; mt < 2; mt++) {
                int r  = wm * 32 + mt * 16;
                int i0 = (r + g) * SKP + ks + t;
                int i8 = (r + g + 8) * SKP + ks + t;
                afh[mt][0] = __float_as_uint(sAh[i0]);
                afh[mt][1] = __float_as_uint(sAh[i8]);
                afh[mt][2] = __float_as_uint(sAh[i0 + 4]);
                afh[mt][3] = __float_as_uint(sAh[i8 + 4]);
                afl[mt][0] = __float_as_uint(sAl[i0]);
                afl[mt][1] = __float_as_uint(sAl[i8]);
                afl[mt][2] = __float_as_uint(sAl[i0 + 4]);
                afl[mt][3] = __float_as_uint(sAl[i8 + 4]);
            }
#pragma unroll
            for (int nt = 0; nt < 8; nt++) {
                int bb = (wn * 64 + nt * 8 + g) * SKP + ks + t;
                uint32_t bfh[2] = { __float_as_uint(sBh[bb]), __float_as_uint(sBh[bb + 4]) };
                uint32_t bfl[2] = { __float_as_uint(sBl[bb]), __float_as_uint(sBl[bb + 4]) };
#pragma unroll
                for (int mt = 0; mt < 2; mt++) {
                    mma_tf32(acc[mt][nt], afh[mt], bfh);
                    mma_tf32(acc[mt][nt], afh[mt], bfl);
                    mma_tf32(acc[mt][nt], afl[mt], bfh);
                }
            }
        }
        __syncthreads();
    }

#pragma unroll
    for (int mt = 0; mt < 2; mt++) {
        int row = m0 + wm * 32 + mt * 16 + g;
        float* r0 = M0out + (long long)b * PQ + (long long)row * HW;
        float* r1 = r0 + 8ll * HW;
#pragma unroll
        for (int nt = 0; nt < 8; nt++) {
            int col = n0 + wn * 64 + nt * 8 + 2 * t;
            float2 v0; v0.x = acc[mt][nt][0]; v0.y = acc[mt][nt][1];
            float2 v1; v1.x = acc[mt][nt][2]; v1.y = acc[mt][nt][3];
            *(float2*)&r0[col] = v0;
            *(float2*)&r1[col] = v1;
        }
    }
}

// ---------------- double-buffered pipelined SGEMM (f32x2 inner loop) ----------------
template<int BM, int BN, int BK, int TM, int TN, bool TA, bool TB>
__device__ __forceinline__ void sgemm_tile(
    const float* __restrict__ Ab, const float* __restrict__ Bb, float* __restrict__ Cb,
    int M, int N, int K, float alpha, float diagAdd, const float* __restrict__ bias)
{
    constexpr int THREADS = (BM / TM) * (BN / TN);
    constexpr int LA4 = BM * BK / (4 * THREADS);
    constexpr int LB4 = BN * BK / (4 * THREADS);
    __shared__ float As[2][BK][BM + 4];
    __shared__ float Bs[2][BK][BN + 4];
    const int tid  = threadIdx.x;
    const int tcol = tid % (BN / TN);
    const int trow = tid / (BN / TN);
    const int m0 = blockIdx.y * BM;
    const int n0 = blockIdx.x * BN;

    float4 stA[LA4], stB[LB4];

    auto loadA = [&](int k0) {
#pragma unroll
        for (int l = 0; l < LA4; l++) {
            int i = tid + l * THREADS;
            if (TA) { int kk = i / (BM / 4); int m = (i % (BM / 4)) * 4;
                      stA[l] = *(const float4*)&Ab[(long long)(k0 + kk) * M + m0 + m]; }
            else    { int m = i / (BK / 4); int kk = (i % (BK / 4)) * 4;
                      stA[l] = *(const float4*)&Ab[(long long)(m0 + m) * K + k0 + kk]; }
        }
    };
    auto loadB = [&](int k0) {
#pragma unroll
        for (int l = 0; l < LB4; l++) {
            int i = tid + l * THREADS;
            if (TB) { int n = i / (BK / 4); int kk = (i % (BK / 4)) * 4;
                      stB[l] = *(const float4*)&Bb[(long long)(n0 + n) * K + k0 + kk]; }
            else    { int kk = i / (BN / 4); int n = (i % (BN / 4)) * 4;
                      stB[l] = *(const float4*)&Bb[(long long)(k0 + kk) * N + n0 + n]; }
        }
    };
    auto storeA = [&](int buf) {
#pragma unroll
        for (int l = 0; l < LA4; l++) {
            int i = tid + l * THREADS;
            if (TA) { int kk = i / (BM / 4); int m = (i % (BM / 4)) * 4;
                      *(float4*)&As[buf][kk][m] = stA[l]; }
            else    { int m = i / (BK / 4); int kk = (i % (BK / 4)) * 4;
                      As[buf][kk + 0][m] = stA[l].x; As[buf][kk + 1][m] = stA[l].y;
                      As[buf][kk + 2][m] = stA[l].z; As[buf][kk + 3][m] = stA[l].w; }
        }
    };
    auto storeB = [&](int buf) {
#pragma unroll
        for (int l = 0; l < LB4; l++) {
            int i = tid + l * THREADS;
            if (TB) { int n = i / (BK / 4); int kk = (i % (BK / 4)) * 4;
                      Bs[buf][kk + 0][n] = stB[l].x; Bs[buf][kk + 1][n] = stB[l].y;
                      Bs[buf][kk + 2][n] = stB[l].z; Bs[buf][kk + 3][n] = stB[l].w; }
            else    { int kk = i / (BN / 4); int n = (i % (BN / 4)) * 4;
                      *(float4*)&Bs[buf][kk][n] = stB[l]; }
        }
    };

    u64 acc[TM][TN / 2];
#pragma unroll
    for (int i = 0; i < TM; i++)
#pragma unroll
        for (int j = 0; j < TN / 2; j++) acc[i][j] = 0ull;

    loadA(0); loadB(0);
    storeA(0); storeB(0);
    __syncthreads();

    int buf = 0;
    for (int k0 = 0; k0 < K; k0 += BK) {
        const bool has_next = (k0 + BK < K);
        if (has_next) { loadA(k0 + BK); loadB(k0 + BK); }
#pragma unroll
        for (int kk = 0; kk < BK; kk++) {
            float ra[TM];
#pragma unroll
            for (int i4 = 0; i4 < TM / 4; i4++) {
                float4 a4 = *(const float4*)&As[buf][kk][trow * TM + i4 * 4];
                ra[i4 * 4 + 0] = a4.x; ra[i4 * 4 + 1] = a4.y;
                ra[i4 * 4 + 2] = a4.z; ra[i4 * 4 + 3] = a4.w;
            }
            u64 rb2[TN / 2];
#pragma unroll
            for (int j4 = 0; j4 < TN / 4; j4++) {
                ulonglong2 b2 = *(const ulonglong2*)&Bs[buf][kk][tcol * TN + j4 * 4];
                rb2[j4 * 2 + 0] = b2.x; rb2[j4 * 2 + 1] = b2.y;
            }
#pragma unroll
            for (int i = 0; i < TM; i++) {
                u64 a2 = pack2(ra[i]);
#pragma unroll
                for (int j = 0; j < TN / 2; j++) ffma2(acc[i][j], a2, rb2[j]);
            }
        }
        if (has_next) { storeA(buf ^ 1); storeB(buf ^ 1); }
        __syncthreads();
        buf ^= 1;
    }

#pragma unroll
    for (int i = 0; i < TM; i++) {
        int gm = m0 + trow * TM + i;
        float bv = bias ? bias[gm] : 0.f;
#pragma unroll
        for (int j = 0; j < TN / 2; j++) {
            float2 v = unpack2(acc[i][j]);
            int gn = n0 + tcol * TN + 2 * j;
            float x = alpha * v.x + bv; if (gm == gn)     x += diagAdd;
            float y = alpha * v.y + bv; if (gm == gn + 1) y += diagAdd;
            float2 o; o.x = x; o.y = y;
            *(float2*)&Cb[(long long)gm * N + gn] = o;
        }
    }
}

template<int BM, int BN, int BK, int TM, int TN, bool TA, bool TB>
__global__ void sgemm_kernel(const float* __restrict__ A, const float* __restrict__ B,
                             float* __restrict__ C,
                             int M, int N, int K,
                             long long sA, long long sB, long long sC,
                             float alpha, float diagAdd,
                             const float* __restrict__ bias, int biasStride)
{
    const float* Ab = A + (long long)blockIdx.z * sA;
    const float* Bb = B + (long long)blockIdx.z * sB;
    float* Cb = C + (long long)blockIdx.z * sC;
    const float* bb = bias ? bias + (long long)blockIdx.z * biasStride : nullptr;
    sgemm_tile<BM, BN, BK, TM, TN, TA, TB>(Ab, Bb, Cb, M, N, K, alpha, diagAdd, bb);
}

__global__ void ns_yz_kernel(const float* __restrict__ Y, const float* __restrict__ T,
                             const float* __restrict__ Z,
                             float* __restrict__ Yn, float* __restrict__ Zn)
{
    int z = blockIdx.z;
    const float *Ab, *Bb; float* Cb;
    if (z < 4) { Ab = Y + (long long)z * CC;       Bb = T + (long long)z * CC;       Cb = Yn + (long long)z * CC; }
    else       { Ab = T + (long long)(z - 4) * CC; Bb = Z + (long long)(z - 4) * CC; Cb = Zn + (long long)(z - 4) * CC; }
    sgemm_tile<64, 64, 16, 4, 4, false, false>(Ab, Bb, Cb, 512, 512, 512, 1.f, 0.f, nullptr);
}

// ---------------- per-channel mean + center ----------------
__global__ void center_kernel(const float* __restrict__ content, const float* __restrict__ style,
                              float* __restrict__ Fcent, float* __restrict__ means)
{
    int c = blockIdx.x, g = blockIdx.y;
    const float* src = (g < 2 ? content + (long long)g * CHW : style + (long long)(g - 2) * CHW)
                       + (long long)c * HW;
    __shared__ float red[256];
    float s = 0.f;
    for (int i = threadIdx.x; i < HW; i += 256) s += src[i];
    red[threadIdx.x] = s; __syncthreads();
    for (int st = 128; st > 0; st >>= 1) {
        if (threadIdx.x < st) red[threadIdx.x] += red[threadIdx.x + st];
        __syncthreads();
    }
    float mean = red[0] * (1.f / HW);
    if (threadIdx.x == 0) means[g * CH + c] = mean;
    float* dst = Fcent + (long long)g * CHW + (long long)c * HW;
    for (int i = threadIdx.x; i < HW; i += 256) dst[i] = src[i] - mean;
}

// ---------------- power iteration ----------------
__global__ void power_kernel(const float* __restrict__ Cov, float* __restrict__ sigma)
{
    int g = blockIdx.x;
    const float* A = Cov + (long long)g * CC;
    __shared__ float v[CH];
    __shared__ float red[CH];
    int t = threadIdx.x;
    v[t] = 1.f + 1e-4f * t;
    __syncthreads();
    float lam = 0.f;
    for (int it = 0; it < 40; it++) {
        float acc = 0.f;
        for (int k = 0; k < CH; k++) acc = fmaf(A[(long long)k * CH + t], v[k], acc);
        __syncthreads();
        red[t] = acc * acc; __syncthreads();
        for (int st = 256; st > 0; st >>= 1) {
            if (t < st) red[t] += red[t + st];
            __syncthreads();
        }
        float n2 = red[0];
        lam = sqrtf(n2);
        float inv = (n2 > 0.f) ? rsqrtf(n2) : 0.f;
        __syncthreads();
        v[t] = acc * inv;
        __syncthreads();
    }
    if (t == 0) sigma[g] = lam * 1.02f + 1e-20f;
}

// ---------------- Newton-Schulz init / rescale ----------------
__global__ void ns_init_kernel(const float* __restrict__ Cov, const float* __restrict__ sigma,
                               float* __restrict__ Y, float* __restrict__ Z)
{
    long long i = (long long)blockIdx.x * blockDim.x + threadIdx.x;
    if (i >= 4 * CC) return;
    int g = (int)(i / CC);
    long long r = i % CC;
    int row = (int)(r / CH), col = (int)(r % CH);
    Y[i] = Cov[i] / sigma[g];
    Z[i] = (row == col) ? 1.f : 0.f;
}

__global__ void scale_kernel(const float* __restrict__ Y, const float* __restrict__ Z,
                             const float* __restrict__ sigma,
                             float* __restrict__ W, float* __restrict__ Cm)
{
    long long i = (long long)blockIdx.x * blockDim.x + threadIdx.x;
    if (i >= 4 * CC) return;
    int g = (int)(i / CC);
    float sq = sqrtf(sigma[g]);
    W[i] = Z[i] / sq;
    if (g >= 2) Cm[i - 2 * CC] = Y[i] * sq;
}

// ---------------- transpose + tf32 hi/lo split ----------------
__global__ void transpose_split_kernel(const float* __restrict__ NC,
                                       float* __restrict__ NSt,
                                       float* __restrict__ NCth, float* __restrict__ NCtl,
                                       float* __restrict__ NSth, float* __restrict__ NStl)
{
    __shared__ float tile[32][33];
    int g = blockIdx.z;
    int p0 = blockIdx.x * 32, c0 = blockIdx.y * 32;
    const float* src = NC + (long long)g * CHW;
    tile[threadIdx.y][threadIdx.x] = src[(long long)(c0 + threadIdx.y) * HW + p0 + threadIdx.x];
    __syncthreads();
    float x = tile[threadIdx.x][threadIdx.y];
    long long o = (long long)(g & 1) * CHW + (long long)(p0 + threadIdx.y) * CH + c0 + threadIdx.x;
    float hi = tf32_rna(x);
    float lo = tf32_rna(x - hi);
    if (g < 2) { NCth[o] = hi; NCtl[o] = lo; }
    else       { NSt[o] = x; NSth[o] = hi; NStl[o] = lo; }
}

// ---------------- per-pixel squared norms ----------------
__global__ void snorm_kernel(const float* __restrict__ NSt, float* __restrict__ snorm)
{
    int gw = (blockIdx.x * blockDim.x + threadIdx.x) >> 5;
    int lane = threadIdx.x & 31;
    if (gw >= 2 * HW) return;
    int b = gw / HW, p = gw % HW;
    const float* row = NSt + (long long)b * CHW + (long long)p * CH;
    float s = 0.f;
    for (int c = lane; c < CH; c += 32) { float v = row[c]; s = fmaf(v, v, s); }
    for (int o = 16; o > 0; o >>= 1) s += __shfl_down_sync(0xffffffff, s, o);
    if (lane == 0) snorm[b * HW + p] = s;
}

__global__ void rknorm_kernel(const float* __restrict__ snorm, float* __restrict__ rk)
{
    int i = blockIdx.x * blockDim.x + threadIdx.x;
    if (i >= 2 * HW) return;
    int b = i / HW, p = i % HW;
    int py = p >> 6, px = p & 63;
    float sum = 0.f;
    for (int u = -1; u <= 1; u++)
        for (int v = -1; v <= 1; v++) {
            int yy = py + u, xx = px + v;
            if ((unsigned)yy < 64u && (unsigned)xx < 64u) sum += snorm[b * HW + yy * 64 + xx];
        }
    rk[i] = 1.f / (sqrtf(sum) + 1e-5f);
}

// ---------------- horizontal diagonal 3-box ----------------
__global__ void boxh_kernel(const float* __restrict__ M0, float* __restrict__ Tb)
{
    long long i = (long long)blockIdx.x * 256 + threadIdx.x;
    int b = blockIdx.y;
    const float* M = M0 + (long long)b * PQ;
    int p = (int)(i >> 12);
    int q = (int)(i & 4095);
    int px = p & 63, qx = q & 63;
    float s = 0.f;
#pragma unroll
    for (int v = -1; v <= 1; v++) {
        if ((unsigned)(px + v) < 64u && (unsigned)(qx + v) < 64u) s += M[i + (long long)v * 4097];
    }
    Tb[(long long)b * PQ + i] = s;
}

// ---------------- vertical diagonal 3-box + partial argmax ----------------
__global__ void argmax_part_kernel(const float* __restrict__ Tb, const float* __restrict__ rk,
                                   float* __restrict__ pbs, int* __restrict__ pbi)
{
    int b = blockIdx.z;
    int q = blockIdx.x * 256 + threadIdx.x;
    int pc = blockIdx.y;
    __shared__ float srk[256];
    srk[threadIdx.x] = rk[b * HW + pc * 256 + threadIdx.x];
    __syncthreads();
    const float* T = Tb + (long long)b * PQ;
    float best = -FLT_MAX; int bi = 0;
    for (int pp = 0; pp < 256; pp++) {
        int p = pc * 256 + pp;
        float s = 0.f;
#pragma unroll
        for (int u = -1; u <= 1; u++) {
            int row = p + 64 * u, col = q + 64 * u;
            if ((unsigned)row < (unsigned)HW && (unsigned)col < (unsigned)HW)
                s += T[(long long)row * HW + col];
        }
        float sc = s * srk[pp];
        if (sc > best) { best = sc; bi = p; }
    }
    pbs[(b * 16 + pc) * HW + q] = best;
    pbi[(b * 16 + pc) * HW + q] = bi;
}

__global__ void argmax_comb_kernel(const float* __restrict__ pbs, const int* __restrict__ pbi,
                                   int* __restrict__ idx)
{
    int i = blockIdx.x * 256 + threadIdx.x;
    if (i >= 2 * HW) return;
    int b = i / HW, q = i % HW;
    float best = -FLT_MAX; int bi = 0;
    for (int k = 0; k < 16; k++) {
        float s = pbs[(b * 16 + k) * HW + q];
        int p = pbi[(b * 16 + k) * HW + q];
        if (s > best || (s == best && p < bi)) { best = s; bi = p; }
    }
    idx[b * HW + q] = bi;
}

// ---------------- gather best patches + overlap-add ----------------
__global__ void gather_kernel(const float* __restrict__ NSt, const int* __restrict__ idx,
                              float* __restrict__ reasT)
{
    int b = blockIdx.y, pix = blockIdx.x;
    int Y = pix >> 6, X = pix & 63;
    __shared__ int sp[9];
    if (threadIdx.x < 9) {
        int dx = threadIdx.x / 3, dy = threadIdx.x % 3;
        int y = Y + 1 - dx, x = X + 1 - dy;
        int pos = -1;
        if ((unsigned)y < 64u && (unsigned)x < 64u) {
            int p = idx[b * HW + y * 64 + x];
            int sy = (p >> 6) + dx - 1, sx = (p & 63) + dy - 1;
            if ((unsigned)sy < 64u && (unsigned)sx < 64u) pos = sy * 64 + sx;
        }
        sp[threadIdx.x] = pos;
    }
    __syncthreads();
    int cy = (Y == 0 || Y == 63) ? 2 : 3;
    int cx = (X == 0 || X == 63) ? 2 : 3;
    float inv = 1.f / (float)(cy * cx);
    const float* base = NSt + (long long)b * CHW;
    float* out = reasT + (long long)b * CHW + (long long)pix * CH;
    for (int c = threadIdx.x; c < CH; c += 128) {
        float a = 0.f;
#pragma unroll
        for (int k = 0; k < 9; k++) {
            int pos = sp[k];
            if (pos >= 0) a += base[(long long)pos * CH + c];
        }
        out[c] = a * inv;
    }
}

// ---------------- host orchestration ----------------
extern "C" void kernel_launch(void* const* d_in, const int* in_sizes, int n_in,
                              void* d_out, int out_size)
{
    (void)in_sizes; (void)n_in; (void)out_size;
    const float* content = (const float*)d_in[0];
    const float* style   = (const float*)d_in[1];
    float* out = (float*)d_out;

    float *Fcent, *means, *Cov, *sigma, *Yb, *Zb, *Tm, *W, *Cm, *NC, *NSt, *snorm, *rk, *M0, *Tb, *pbs, *reasT;
    float *NCth, *NCtl, *NSth, *NStl;
    int *idx, *pbi;
    cudaGetSymbolAddress((void**)&Fcent, g_Fcent);
    cudaGetSymbolAddress((void**)&means, g_means);
    cudaGetSymbolAddress((void**)&Cov,   g_Cov);
    cudaGetSymbolAddress((void**)&sigma, g_sigma);
    cudaGetSymbolAddress((void**)&Yb,    g_Ybuf);
    cudaGetSymbolAddress((void**)&Zb,    g_Zbuf);
    cudaGetSymbolAddress((void**)&Tm,    g_Tm);
    cudaGetSymbolAddress((void**)&W,     g_W);
    cudaGetSymbolAddress((void**)&Cm,    g_Cm);
    cudaGetSymbolAddress((void**)&NC,    g_NC);
    cudaGetSymbolAddress((void**)&NSt,   g_NSt);
    cudaGetSymbolAddress((void**)&NCth,  g_NCth);
    cudaGetSymbolAddress((void**)&NCtl,  g_NCtl);
    cudaGetSymbolAddress((void**)&NSth,  g_NSth);
    cudaGetSymbolAddress((void**)&NStl,  g_NStl);
    cudaGetSymbolAddress((void**)&snorm, g_snorm);
    cudaGetSymbolAddress((void**)&rk,    g_rk);
    cudaGetSymbolAddress((void**)&M0,    g_M0);
    cudaGetSymbolAddress((void**)&Tb,    g_Tb);
    cudaGetSymbolAddress((void**)&idx,   g_idx);
    cudaGetSymbolAddress((void**)&pbs,   g_pbs);
    cudaGetSymbolAddress((void**)&pbi,   g_pbi);
    cudaGetSymbolAddress((void**)&reasT, g_reasT);

    cudaFuncSetAttribute(m0_mma_kernel, cudaFuncAttributeMaxDynamicSharedMemorySize, M0_SMEM);

    // 1) center
    center_kernel<<<dim3(CH, 4), 256>>>(content, style, Fcent, means);

    // 2) covariances
    sgemm_kernel<64, 64, 16, 4, 4, false, true><<<dim3(8, 8, 4), 256>>>(
        Fcent, Fcent, Cov, 512, 512, 4096, CHW, CHW, CC, 1.f / 4095.f, 0.f, nullptr, 0);

    // 3) lambda_max
    power_kernel<<<4, 512>>>(Cov, sigma);

    // 4) Newton-Schulz (5 iterations — residual ~5e-8)
    ns_init_kernel<<<4096, 256>>>(Cov, sigma, Yb, Zb);
    float* Yc = Yb;            float* Yn = Yb + 4 * CC;
    float* Zc = Zb;            float* Zn = Zb + 4 * CC;
    for (int it = 0; it < 5; it++) {
        sgemm_kernel<64, 64, 16, 4, 4, false, false><<<dim3(8, 8, 4), 256>>>(
            Zc, Yc, Tm, 512, 512, 512, CC, CC, CC, -0.5f, 1.5f, nullptr, 0);
        ns_yz_kernel<<<dim3(8, 8, 8), 256>>>(Yc, Tm, Zc, Yn, Zn);
        float* t;
        t = Yc; Yc = Yn; Yn = t;
        t = Zc; Zc = Zn; Zn = t;
    }
    // 5) rescale
    scale_kernel<<<4096, 256>>>(Yc, Zc, sigma, W, Cm);

    // 6) whitening: NC[g] = W[g] @ Fcent[g]
    sgemm_kernel<128, 128, 16, 8, 8, false, false><<<dim3(32, 4, 4), 256>>>(
        W, Fcent, NC, 512, 4096, 512, CC, CHW, CHW, 1.f, 0.f, nullptr, 0);

    // 7) transpose + tf32 split + patch norms
    transpose_split_kernel<<<dim3(128, 16, 4), dim3(32, 32)>>>(NC, NSt, NCth, NCtl, NSth, NStl);
    snorm_kernel<<<1024, 256>>>(NSt, snorm);
    rknorm_kernel<<<32, 256>>>(snorm, rk);

    // 8) M0[b] = ns[b]^T @ nc[b] via warp-level tf32 mma (3xTF32, cp.async pipelined)
    m0_mma_kernel<<<dim3(32, 32, 2), 256, M0_SMEM>>>(NSth, NStl, NCth, NCtl, M0);

    // 9) box filter + argmax
    boxh_kernel<<<dim3(65536, 2), 256>>>(M0, Tb);
    argmax_part_kernel<<<dim3(16, 16, 2), 256>>>(Tb, rk, pbs, pbi);
    argmax_comb_kernel<<<32, 256>>>(pbs, pbi, idx);

    // 10) gather + overlap-add
    gather_kernel<<<dim3(4096, 2), 128>>>(NSt, idx, reasT);

    // 11) color
    sgemm_kernel<128, 128, 16, 8, 8, false, true><<<dim3(32, 4, 2), 256>>>(
        Cm, reasT, out, 512, 4096, 512, CC, CHW, CHW, 1.f, 0.f, means + 2 * CH, CH);
}